// round 14
// baseline (speedup 1.0000x reference)
#include <cuda_runtime.h>
#include <cuda_bf16.h>
#include <math.h>
#include <stdint.h>

#define NN 50000
#define NE 500000
#define HID 64
#define HEADS 8
#define NCLS 10
#define MPAD 50048            // 391 * 128
#define F0ROWS 30080          // 235*128
#define F1ROWS 20096          // 157*128
#define F0SZ (F0ROWS * 256)
#define FSZ  (F0SZ + F1ROWS * 128)
#define NBLK 196              // scan blocks: 196*256 = 50176 >= NN

// ---------------- scratch -----------------------------------------------
__device__ float g_bufA[(size_t)NN * 512];
__device__ float g_bufB[(size_t)NN * 16];
__device__ float g_elA[NN * HEADS];
__device__ float g_erA[NN * HEADS];
__device__ float g_elB[NN * HEADS];
__device__ float g_erB[NN * HEADS];
__device__ int   g_deg[NN];
__device__ int   g_rowptr[NN + 1];
__device__ int   g_cursor[NN];
__device__ int   g_csrsrc[NE];
__device__ int   g_blksum[256];
__device__ int   g_blkoff[256];
__device__ __nv_bfloat16 g_f_hi[FSZ];
__device__ __nv_bfloat16 g_f_lo[FSZ];
__device__ __nv_bfloat16 g_h_hi[(size_t)MPAD * 64];
__device__ __nv_bfloat16 g_h_lo[(size_t)MPAD * 64];
__device__ __nv_bfloat16 g_a_hi[(size_t)MPAD * 512];
__device__ __nv_bfloat16 g_a_lo[(size_t)MPAD * 512];
__device__ __nv_bfloat16 g_wf0_hi[64 * 256], g_wf0_lo[64 * 256];
__device__ __nv_bfloat16 g_wf1_hi[64 * 128], g_wf1_lo[64 * 128];
__device__ __nv_bfloat16 g_w0t_hi[512 * 64], g_w0t_lo[512 * 64];
__device__ __nv_bfloat16 g_w1t_hi[512 * 512], g_w1t_lo[512 * 512];

// ---------------- PTX helpers --------------------------------------------
__device__ __forceinline__ uint32_t smem_u32(const void* p) {
    uint32_t a;
    asm("{ .reg .u64 t; cvta.to.shared.u64 t, %1; cvt.u32.u64 %0, t; }" : "=r"(a) : "l"(p));
    return a;
}
__device__ __forceinline__ void cp_async16(uint32_t s, const void* g) {
    asm volatile("cp.async.cg.shared.global [%0], [%1], 16;" :: "r"(s), "l"(g));
}
#define CP_COMMIT() asm volatile("cp.async.commit_group;" ::: "memory")

__device__ __forceinline__ void ldsm_x4(uint32_t& r0, uint32_t& r1, uint32_t& r2, uint32_t& r3,
                                        uint32_t addr) {
    asm volatile("ldmatrix.sync.aligned.m8n8.x4.shared.b16 {%0,%1,%2,%3}, [%4];"
                 : "=r"(r0), "=r"(r1), "=r"(r2), "=r"(r3) : "r"(addr));
}
__device__ __forceinline__ void mma_bf16(float* d, const uint32_t* a, const uint32_t* b) {
    asm volatile(
        "mma.sync.aligned.m16n8k16.row.col.f32.bf16.bf16.f32 "
        "{%0,%1,%2,%3}, {%4,%5,%6,%7}, {%8,%9}, {%0,%1,%2,%3};"
        : "+f"(d[0]), "+f"(d[1]), "+f"(d[2]), "+f"(d[3])
        : "r"(a[0]), "r"(a[1]), "r"(a[2]), "r"(a[3]), "r"(b[0]), "r"(b[1]));
}

// ---------------- graph preprocessing ---------------------------------------
__global__ void k_zero_deg() {
    int i = blockIdx.x * blockDim.x + threadIdx.x;
    if (i < NN) g_deg[i] = 0;
}
__global__ void k_zero_el() {
    int i = blockIdx.x * blockDim.x + threadIdx.x;
    if (i < NN * HEADS) {
        g_elA[i] = 0.f; g_erA[i] = 0.f;
        g_elB[i] = 0.f; g_erB[i] = 0.f;
    }
}
__global__ void k_count(const int* __restrict__ dst, int E) {
    int e = blockIdx.x * blockDim.x + threadIdx.x;
    if (e < E) atomicAdd(&g_deg[dst[e]], 1);
}
__global__ void k_scan1() {
    __shared__ int sh[256];
    int b = blockIdx.x, t = threadIdx.x;
    int i = b * 256 + t;
    int v = (i < NN) ? g_deg[i] : 0;
    sh[t] = v;
    __syncthreads();
#pragma unroll
    for (int off = 1; off < 256; off <<= 1) {
        int x = (t >= off) ? sh[t - off] : 0;
        __syncthreads();
        sh[t] += x;
        __syncthreads();
    }
    if (i < NN) g_rowptr[i] = sh[t] - v;
    if (t == 255) g_blksum[b] = sh[255];
}
__global__ void k_scan2() {
    __shared__ int sh[256];
    int t = threadIdx.x;
    int v = (t < NBLK) ? g_blksum[t] : 0;
    sh[t] = v;
    __syncthreads();
#pragma unroll
    for (int off = 1; off < 256; off <<= 1) {
        int x = (t >= off) ? sh[t - off] : 0;
        __syncthreads();
        sh[t] += x;
        __syncthreads();
    }
    if (t < NBLK) g_blkoff[t] = sh[t] - v;
    if (t == 255) g_rowptr[NN] = sh[255];
}
__global__ void k_scan3() {
    int i = blockIdx.x * blockDim.x + threadIdx.x;
    if (i < NN) {
        int r = g_rowptr[i] + g_blkoff[i >> 8];
        g_rowptr[i] = r;
        g_cursor[i] = r;
    }
}
__global__ void k_scatter(const int* __restrict__ src, const int* __restrict__ dst, int E) {
    int e = blockIdx.x * blockDim.x + threadIdx.x;
    if (e < E) {
        int pos = atomicAdd(&g_cursor[dst[e]], 1);
        g_csrsrc[pos] = src[e];
    }
}

// ---------------- weight transpose + bf16 split -----------------------------
__global__ void k_tsplit(const float* __restrict__ W, __nv_bfloat16* __restrict__ Thi,
                         __nv_bfloat16* __restrict__ Tlo, int K, int N)
{
    __shared__ float s[32][33];
    int tx = threadIdx.x, ty = threadIdx.y;
    int k = blockIdx.y * 32 + ty, n = blockIdx.x * 32 + tx;
    s[ty][tx] = W[(size_t)k * N + n];
    __syncthreads();
    int n2 = blockIdx.x * 32 + ty, k2 = blockIdx.y * 32 + tx;
    float v = s[tx][ty];
    __nv_bfloat16 h = __float2bfloat16(v);
    Thi[(size_t)n2 * K + k2] = h;
    Tlo[(size_t)n2 * K + k2] = __float2bfloat16(v - __bfloat162float(h));
}

__global__ void k_asplit(const float* __restrict__ A, __nv_bfloat16* __restrict__ hi,
                         __nv_bfloat16* __restrict__ lo, int count)
{
    int i = (blockIdx.x * blockDim.x + threadIdx.x) * 4;
    if (i >= count) return;
    float4 v = *reinterpret_cast<const float4*>(A + i);
    __nv_bfloat162 h0, h1, l0, l1;
    h0.x = __float2bfloat16(v.x); h0.y = __float2bfloat16(v.y);
    h1.x = __float2bfloat16(v.z); h1.y = __float2bfloat16(v.w);
    l0.x = __float2bfloat16(v.x - __bfloat162float(h0.x));
    l0.y = __float2bfloat16(v.y - __bfloat162float(h0.y));
    l1.x = __float2bfloat16(v.z - __bfloat162float(h1.x));
    l1.y = __float2bfloat16(v.w - __bfloat162float(h1.y));
    *reinterpret_cast<__nv_bfloat162*>(hi + i) = h0;
    *reinterpret_cast<__nv_bfloat162*>(hi + i + 2) = h1;
    *reinterpret_cast<__nv_bfloat162*>(lo + i) = l0;
    *reinterpret_cast<__nv_bfloat162*>(lo + i + 2) = l1;
}

// ---------------- generalized bf16 3x-split mma GEMM -------------------------
// 4-stage cp.async pipeline, 3-pass MMA (hh/hl/lh).
// ldsm ordered so pass-1 deps (ahi, bhi) issue FIRST; alo/blo latency
// hides under pass-1 MMAs (all asm volatile => order preserved).
#define ROWB 48
#define TILEB (128 * ROWB)
#define STG 4
template <int KDIM, int BN, bool FUSE, bool SPLIT_OUT>
__global__ __launch_bounds__(256) void k_mma(
    const __nv_bfloat16* __restrict__ Ahi, const __nv_bfloat16* __restrict__ Alo,
    const __nv_bfloat16* __restrict__ Bhi, const __nv_bfloat16* __restrict__ Blo,
    float* __restrict__ C,
    __nv_bfloat16* __restrict__ Ohi, __nv_bfloat16* __restrict__ Olo,
    const float* __restrict__ bias,
    const float* __restrict__ al, const float* __restrict__ ar,
    float* __restrict__ el, float* __restrict__ er,
    int M)
{
    constexpr int NCH = KDIM / 16;
    constexpr int MI = (BN == 128) ? 4 : 2;
    constexpr int BTILE = BN * ROWB;
    constexpr int BUFB = 2 * TILEB + 2 * BTILE;
    extern __shared__ char smem[];
    uint32_t sb = smem_u32(smem);

    const int tid = threadIdx.x;
    const int wid = tid >> 5, lane = tid & 31;
    const int bm = blockIdx.y * 128;
    const int bn = blockIdx.x * BN;
    const int wm = (BN == 128) ? (wid & 1) * 64 : (wid & 3) * 32;
    const int wn = (BN == 128) ? (wid >> 1) * 32 : (wid >> 2) * 32;

    const int lrow = tid >> 1, lhalf = tid & 1;
    const bool bOK = (BN == 128) || (tid < 128);
    const __nv_bfloat16* gAh = Ahi + (size_t)(bm + lrow) * KDIM + lhalf * 8;
    const __nv_bfloat16* gAl = Alo + (size_t)(bm + lrow) * KDIM + lhalf * 8;
    const int brow = bOK ? lrow : 0;
    const __nv_bfloat16* gBh = Bhi + (size_t)(bn + brow) * KDIM + lhalf * 8;
    const __nv_bfloat16* gBl = Blo + (size_t)(bn + brow) * KDIM + lhalf * 8;
    const uint32_t sdst = lrow * ROWB + lhalf * 16;
    const uint32_t sdstB = brow * ROWB + lhalf * 16;

    auto load_chunk = [&](int c) {
        uint32_t base = sb + (c % STG) * BUFB;
        int k0 = c * 16;
        cp_async16(base + sdst,         gAh + k0);
        cp_async16(base + TILEB + sdst, gAl + k0);
        if (bOK) {
            cp_async16(base + 2 * TILEB + sdstB,         gBh + k0);
            cp_async16(base + 2 * TILEB + BTILE + sdstB, gBl + k0);
        }
    };

    float acc[MI][4][4];
#pragma unroll
    for (int i = 0; i < MI; i++)
#pragma unroll
        for (int j = 0; j < 4; j++)
#pragma unroll
            for (int k = 0; k < 4; k++) acc[i][j][k] = 0.f;

#pragma unroll
    for (int c = 0; c < STG - 1 && c < NCH; c++) {
        load_chunk(c);
        CP_COMMIT();
    }

    const uint32_t a_off = (wm + (lane & 15)) * ROWB + (lane >> 4) * 16;
    const uint32_t b_off = (wn + (lane & 7) + ((lane >> 4) << 3)) * ROWB + (((lane >> 3) & 1) * 16);

    for (int c = 0; c < NCH; c++) {
        const uint32_t base = sb + (c % STG) * BUFB;
        asm volatile("cp.async.wait_group %0;" :: "n"(STG - 2));
        __syncthreads();

        if (c + STG - 1 < NCH) load_chunk(c + STG - 1);
        CP_COMMIT();

        uint32_t ahi[MI][4], alo[MI][4], bhi[4][2], blo[4][2];
        // pass-1 dependencies first: ahi then bhi
#pragma unroll
        for (int mi = 0; mi < MI; mi++)
            ldsm_x4(ahi[mi][0], ahi[mi][1], ahi[mi][2], ahi[mi][3],
                    base + mi * 16 * ROWB + a_off);
#pragma unroll
        for (int p = 0; p < 2; p++) {
            uint32_t r0, r1, r2, r3;
            ldsm_x4(r0, r1, r2, r3, base + 2 * TILEB + p * 16 * ROWB + b_off);
            bhi[p * 2][0] = r0; bhi[p * 2][1] = r1;
            bhi[p * 2 + 1][0] = r2; bhi[p * 2 + 1][1] = r3;
        }
        // pass-2/3 dependencies issued next; latency hides under pass 1
#pragma unroll
        for (int mi = 0; mi < MI; mi++)
            ldsm_x4(alo[mi][0], alo[mi][1], alo[mi][2], alo[mi][3],
                    base + TILEB + mi * 16 * ROWB + a_off);
#pragma unroll
        for (int p = 0; p < 2; p++) {
            uint32_t r0, r1, r2, r3;
            ldsm_x4(r0, r1, r2, r3, base + 2 * TILEB + BTILE + p * 16 * ROWB + b_off);
            blo[p * 2][0] = r0; blo[p * 2][1] = r1;
            blo[p * 2 + 1][0] = r2; blo[p * 2 + 1][1] = r3;
        }

        // 3 dependency-free passes
#pragma unroll
        for (int mi = 0; mi < MI; mi++)
#pragma unroll
            for (int nb = 0; nb < 4; nb++)
                mma_bf16(acc[mi][nb], ahi[mi], bhi[nb]);
#pragma unroll
        for (int mi = 0; mi < MI; mi++)
#pragma unroll
            for (int nb = 0; nb < 4; nb++)
                mma_bf16(acc[mi][nb], ahi[mi], blo[nb]);
#pragma unroll
        for (int mi = 0; mi < MI; mi++)
#pragma unroll
            for (int nb = 0; nb < 4; nb++)
                mma_bf16(acc[mi][nb], alo[mi], bhi[nb]);
    }

    const int g = lane >> 2, t = lane & 3;

    if (SPLIT_OUT) {
#pragma unroll
        for (int mi = 0; mi < MI; mi++) {
            int r0 = bm + wm + mi * 16 + g;
            int r1 = r0 + 8;
#pragma unroll
            for (int nb = 0; nb < 4; nb++) {
                int col = wn + nb * 8 + 2 * t;
                float b0 = bias[col], b1 = bias[col + 1];
#pragma unroll
                for (int rr = 0; rr < 2; rr++) {
                    int r = rr ? r1 : r0;
                    if (r < M) {
                        float v0 = acc[mi][nb][rr * 2 + 0] + b0;
                        float v1 = acc[mi][nb][rr * 2 + 1] + b1;
                        __nv_bfloat162 h2, l2;
                        h2.x = __float2bfloat16(v0); h2.y = __float2bfloat16(v1);
                        l2.x = __float2bfloat16(v0 - __bfloat162float(h2.x));
                        l2.y = __float2bfloat16(v1 - __bfloat162float(h2.y));
                        *reinterpret_cast<__nv_bfloat162*>(Ohi + (size_t)r * BN + col) = h2;
                        *reinterpret_cast<__nv_bfloat162*>(Olo + (size_t)r * BN + col) = l2;
                    }
                }
            }
        }
    } else {
#pragma unroll
        for (int mi = 0; mi < MI; mi++) {
            int r0 = bm + wm + mi * 16 + g;
            int r1 = r0 + 8;
#pragma unroll
            for (int nb = 0; nb < 4; nb++) {
                int col = bn + wn + nb * 8 + 2 * t;
                if (r0 < M)
                    *reinterpret_cast<float2*>(C + (size_t)r0 * 512 + col) =
                        make_float2(acc[mi][nb][0], acc[mi][nb][1]);
                if (r1 < M)
                    *reinterpret_cast<float2*>(C + (size_t)r1 * 512 + col) =
                        make_float2(acc[mi][nb][2], acc[mi][nb][3]);
            }
        }
        if (FUSE) {
            int hh = (bn + wn) >> 6;
            float av[4][2], rv[4][2];
#pragma unroll
            for (int nb = 0; nb < 4; nb++)
#pragma unroll
                for (int k = 0; k < 2; k++) {
                    int colh = (wn & 63) + nb * 8 + 2 * t + k;
                    av[nb][k] = al[hh * 64 + colh];
                    rv[nb][k] = ar[hh * 64 + colh];
                }
#pragma unroll
            for (int mi = 0; mi < MI; mi++) {
                float pel0 = 0.f, per0 = 0.f, pel1 = 0.f, per1 = 0.f;
#pragma unroll
                for (int nb = 0; nb < 4; nb++) {
                    pel0 += acc[mi][nb][0] * av[nb][0] + acc[mi][nb][1] * av[nb][1];
                    per0 += acc[mi][nb][0] * rv[nb][0] + acc[mi][nb][1] * rv[nb][1];
                    pel1 += acc[mi][nb][2] * av[nb][0] + acc[mi][nb][3] * av[nb][1];
                    per1 += acc[mi][nb][2] * rv[nb][0] + acc[mi][nb][3] * rv[nb][1];
                }
#pragma unroll
                for (int off = 1; off <= 2; off <<= 1) {
                    pel0 += __shfl_xor_sync(0xffffffffu, pel0, off);
                    per0 += __shfl_xor_sync(0xffffffffu, per0, off);
                    pel1 += __shfl_xor_sync(0xffffffffu, pel1, off);
                    per1 += __shfl_xor_sync(0xffffffffu, per1, off);
                }
                if (t == 0) {
                    int r0 = bm + wm + mi * 16 + g;
                    int r1 = r0 + 8;
                    if (r0 < M) {
                        atomicAdd(&el[r0 * HEADS + hh], pel0);
                        atomicAdd(&er[r0 * HEADS + hh], per0);
                    }
                    if (r1 < M) {
                        atomicAdd(&el[r1 * HEADS + hh], pel1);
                        atomicAdd(&er[r1 * HEADS + hh], per1);
                    }
                }
            }
        }
    }
}

// ---------------- fused edge-softmax + aggregation ---------------------------
__device__ __forceinline__ float lrelu(float x) { return x > 0.f ? x : 0.2f * x; }

__global__ void k_attn(const float* __restrict__ feat, const float* __restrict__ bias,
                       const float* __restrict__ el, const float* __restrict__ er,
                       __nv_bfloat16* __restrict__ Ohi, __nv_bfloat16* __restrict__ Olo)
{
    int n = blockIdx.x;
    int h = threadIdx.y;
    int lane = threadIdx.x;
    int start = g_rowptr[n], end = g_rowptr[n + 1];
    int deg = end - start;
    float er_h = er[n * HEADS + h];

    float ax = 0.f, ay = 0.f;

    if (deg <= 32) {
        int s = 0;
        float e = -INFINITY;
        if (lane < deg) {
            s = g_csrsrc[start + lane];
            e = lrelu(el[s * HEADS + h] + er_h);
        }
        float m = e;
#pragma unroll
        for (int o = 16; o; o >>= 1) m = fmaxf(m, __shfl_xor_sync(0xffffffffu, m, o));
        float ws = (lane < deg) ? __expf(e - m) : 0.f;
        float dsum = ws;
#pragma unroll
        for (int o = 16; o; o >>= 1) dsum += __shfl_xor_sync(0xffffffffu, dsum, o);
        float w = ws / fmaxf(dsum, 1e-9f);

        int j = 0;
        for (; j + 4 <= deg; j += 4) {
            int   s0 = __shfl_sync(0xffffffffu, s, j + 0);
            int   s1 = __shfl_sync(0xffffffffu, s, j + 1);
            int   s2 = __shfl_sync(0xffffffffu, s, j + 2);
            int   s3 = __shfl_sync(0xffffffffu, s, j + 3);
            float w0 = __shfl_sync(0xffffffffu, w, j + 0);
            float w1 = __shfl_sync(0xffffffffu, w, j + 1);
            float w2 = __shfl_sync(0xffffffffu, w, j + 2);
            float w3 = __shfl_sync(0xffffffffu, w, j + 3);
            float2 v0 = *reinterpret_cast<const float2*>(feat + (size_t)s0 * 512 + h * 64 + lane * 2);
            float2 v1 = *reinterpret_cast<const float2*>(feat + (size_t)s1 * 512 + h * 64 + lane * 2);
            float2 v2 = *reinterpret_cast<const float2*>(feat + (size_t)s2 * 512 + h * 64 + lane * 2);
            float2 v3 = *reinterpret_cast<const float2*>(feat + (size_t)s3 * 512 + h * 64 + lane * 2);
            ax += w0 * v0.x + w1 * v1.x + w2 * v2.x + w3 * v3.x;
            ay += w0 * v0.y + w1 * v1.y + w2 * v2.y + w3 * v3.y;
        }
        for (; j < deg; j++) {
            int   sj = __shfl_sync(0xffffffffu, s, j);
            float wj = __shfl_sync(0xffffffffu, w, j);
            float2 v = *reinterpret_cast<const float2*>(feat + (size_t)sj * 512 + h * 64 + lane * 2);
            ax += wj * v.x; ay += wj * v.y;
        }
    } else {
        float m = -INFINITY;
        for (int j = start + lane; j < end; j += 32)
            m = fmaxf(m, lrelu(el[g_csrsrc[j] * HEADS + h] + er_h));
#pragma unroll
        for (int o = 16; o; o >>= 1) m = fmaxf(m, __shfl_xor_sync(0xffffffffu, m, o));

        float dsum = 0.f;
        for (int j = start + lane; j < end; j += 32)
            dsum += __expf(lrelu(el[g_csrsrc[j] * HEADS + h] + er_h) - m);
#pragma unroll
        for (int o = 16; o; o >>= 1) dsum += __shfl_xor_sync(0xffffffffu, dsum, o);
        float inv = 1.0f / fmaxf(dsum, 1e-9f);

        for (int j0 = start; j0 < end; j0 += 32) {
            int jmax = end - j0; if (jmax > 32) jmax = 32;
            int s_l = 0; float w_l = 0.f;
            if (lane < jmax) {
                s_l = g_csrsrc[j0 + lane];
                w_l = __expf(lrelu(el[s_l * HEADS + h] + er_h) - m) * inv;
            }
            for (int jj = 0; jj < jmax; jj++) {
                int   sj = __shfl_sync(0xffffffffu, s_l, jj);
                float wj = __shfl_sync(0xffffffffu, w_l, jj);
                float2 v = *reinterpret_cast<const float2*>(feat + (size_t)sj * 512 + h * 64 + lane * 2);
                ax += wj * v.x; ay += wj * v.y;
            }
        }
    }

    float vx = ax + bias[h * 64 + lane * 2];
    float vy = ay + bias[h * 64 + lane * 2 + 1];
    vx = vx > 0.f ? vx : (__expf(vx) - 1.f);
    vy = vy > 0.f ? vy : (__expf(vy) - 1.f);
    __nv_bfloat162 h2, l2;
    h2.x = __float2bfloat16(vx); h2.y = __float2bfloat16(vy);
    l2.x = __float2bfloat16(vx - __bfloat162float(h2.x));
    l2.y = __float2bfloat16(vy - __bfloat162float(h2.y));
    size_t o = (size_t)n * 512 + h * 64 + lane * 2;
    *reinterpret_cast<__nv_bfloat162*>(Ohi + o) = h2;
    *reinterpret_cast<__nv_bfloat162*>(Olo + o) = l2;
}

// ---------------- skinny GEMM + fused el/er (layer 2) ------------------------
__global__ __launch_bounds__(256) void k_gemm_n10(
    const __nv_bfloat16* __restrict__ Ahi, const __nv_bfloat16* __restrict__ Alo,
    const float* __restrict__ B, float* __restrict__ C,
    const float* __restrict__ al2, const float* __restrict__ ar2,
    float* __restrict__ el, float* __restrict__ er, int M)
{
    __shared__ float Bs[512 * 10];
    int tid = threadIdx.x;
    for (int i = tid; i < 512 * 10; i += 256) Bs[i] = B[i];
    __syncthreads();
    int warp = tid >> 5, lane = tid & 31;
    int row = blockIdx.x * 8 + warp;
    if (row >= M) return;
    float acc[10];
#pragma unroll
    for (int c = 0; c < 10; c++) acc[c] = 0.0f;
#pragma unroll
    for (int i = 0; i < 8; i++) {
        int k = lane * 2 + i * 64;
        __nv_bfloat162 h2 = *reinterpret_cast<const __nv_bfloat162*>(Ahi + (size_t)row * 512 + k);
        __nv_bfloat162 l2 = *reinterpret_cast<const __nv_bfloat162*>(Alo + (size_t)row * 512 + k);
        float a0 = __bfloat162float(h2.x) + __bfloat162float(l2.x);
        float a1 = __bfloat162float(h2.y) + __bfloat162float(l2.y);
#pragma unroll
        for (int c = 0; c < 10; c++)
            acc[c] += a0 * Bs[k * 10 + c] + a1 * Bs[(k + 1) * 10 + c];
    }
#pragma unroll
    for (int c = 0; c < 10; c++)
#pragma unroll
        for (int o = 16; o; o >>= 1) acc[c] += __shfl_xor_sync(0xffffffffu, acc[c], o);
    if (lane == 0) {
        float e_l = 0.f, e_r = 0.f;
#pragma unroll
        for (int c = 0; c < 10; c++) {
            C[(size_t)row * 10 + c] = acc[c];
            e_l += acc[c] * al2[c];
            e_r += acc[c] * ar2[c];
        }
        el[row] = e_l;
        er[row] = e_r;
    }
}

// ---------------- layer-2 agg (D=10, f32 out) --------------------------------
__global__ void k_agg10(const float* __restrict__ feat, const float* __restrict__ bias,
                        const float* __restrict__ el, const float* __restrict__ er,
                        float* __restrict__ out)
{
    int n = blockIdx.x;
    int lane = threadIdx.x;
    int start = g_rowptr[n], end = g_rowptr[n + 1];
    float er_h = er[n];

    float m = -INFINITY;
    for (int j = start + lane; j < end; j += 32)
        m = fmaxf(m, lrelu(el[g_csrsrc[j]] + er_h));
#pragma unroll
    for (int o = 16; o; o >>= 1) m = fmaxf(m, __shfl_xor_sync(0xffffffffu, m, o));

    float dsum = 0.f;
    for (int j = start + lane; j < end; j += 32)
        dsum += __expf(lrelu(el[g_csrsrc[j]] + er_h) - m);
#pragma unroll
    for (int o = 16; o; o >>= 1) dsum += __shfl_xor_sync(0xffffffffu, dsum, o);
    float inv = 1.0f / fmaxf(dsum, 1e-9f);

    float acc = 0.f;
    for (int j0 = start; j0 < end; j0 += 32) {
        int jmax = end - j0; if (jmax > 32) jmax = 32;
        int s_l = 0; float w_l = 0.f;
        if (lane < jmax) {
            s_l = g_csrsrc[j0 + lane];
            w_l = __expf(lrelu(el[s_l] + er_h) - m);
        }
        for (int jj = 0; jj < jmax; jj++) {
            int   s = __shfl_sync(0xffffffffu, s_l, jj);
            float w = __shfl_sync(0xffffffffu, w_l, jj);
            if (lane < NCLS) acc += w * feat[(size_t)s * NCLS + lane];
        }
    }
    if (lane < NCLS) out[(size_t)n * NCLS + lane] = acc * inv + bias[lane];
}

// ---------------- launcher ----------------------------------------------------
extern "C" void kernel_launch(void* const* d_in, const int* in_sizes, int n_in,
                              void* d_out, int out_size)
{
    const float* feat0 = (const float*)d_in[0];
    const float* feat1 = (const float*)d_in[1];
    const float* fc0w  = (const float*)d_in[2];
    const float* fc0b  = (const float*)d_in[3];
    const float* fc1w  = (const float*)d_in[4];
    const float* fc1b  = (const float*)d_in[5];
    const float* W0    = (const float*)d_in[6];
    const float* al0   = (const float*)d_in[7];
    const float* ar0   = (const float*)d_in[8];
    const float* b0    = (const float*)d_in[9];
    const float* W1    = (const float*)d_in[10];
    const float* al1   = (const float*)d_in[11];
    const float* ar1   = (const float*)d_in[12];
    const float* b1    = (const float*)d_in[13];
    const float* W2    = (const float*)d_in[14];
    const float* al2   = (const float*)d_in[15];
    const float* ar2   = (const float*)d_in[16];
    const float* b2    = (const float*)d_in[17];
    const int*   ei    = (const int*)d_in[18];

    const int E = in_sizes[18] / 2;
    const int M0 = in_sizes[0] / 256;   // 30000
    const int M1 = in_sizes[1] / 128;   // 20000
    const int* src = ei;
    const int* dst = ei + E;

    float *bufA, *bufB, *elA, *erA, *elB, *erB;
    __nv_bfloat16 *fhi, *flo, *hhi, *hlo, *ahi, *alo;
    __nv_bfloat16 *wf0h, *wf0l, *wf1h, *wf1l, *w0th, *w0tl, *w1th, *w1tl;
    cudaGetSymbolAddress((void**)&bufA, g_bufA);
    cudaGetSymbolAddress((void**)&bufB, g_bufB);
    cudaGetSymbolAddress((void**)&elA,  g_elA);
    cudaGetSymbolAddress((void**)&erA,  g_erA);
    cudaGetSymbolAddress((void**)&elB,  g_elB);
    cudaGetSymbolAddress((void**)&erB,  g_erB);
    cudaGetSymbolAddress((void**)&fhi,  g_f_hi);
    cudaGetSymbolAddress((void**)&flo,  g_f_lo);
    cudaGetSymbolAddress((void**)&hhi,  g_h_hi);
    cudaGetSymbolAddress((void**)&hlo,  g_h_lo);
    cudaGetSymbolAddress((void**)&ahi,  g_a_hi);
    cudaGetSymbolAddress((void**)&alo,  g_a_lo);
    cudaGetSymbolAddress((void**)&wf0h, g_wf0_hi);
    cudaGetSymbolAddress((void**)&wf0l, g_wf0_lo);
    cudaGetSymbolAddress((void**)&wf1h, g_wf1_hi);
    cudaGetSymbolAddress((void**)&wf1l, g_wf1_lo);
    cudaGetSymbolAddress((void**)&w0th, g_w0t_hi);
    cudaGetSymbolAddress((void**)&w0tl, g_w0t_lo);
    cudaGetSymbolAddress((void**)&w1th, g_w1t_hi);
    cudaGetSymbolAddress((void**)&w1tl, g_w1t_lo);

    float* outp = (float*)d_out;

    constexpr int SMEM_L = STG * (2 * TILEB + 2 * 128 * ROWB);   // 98304
    constexpr int SMEM_P = STG * (2 * TILEB + 2 * 64 * ROWB);    // 73728
    cudaFuncSetAttribute((const void*)&k_mma<256, 64, false, true>,
                         cudaFuncAttributeMaxDynamicSharedMemorySize, SMEM_P);
    cudaFuncSetAttribute((const void*)&k_mma<128, 64, false, true>,
                         cudaFuncAttributeMaxDynamicSharedMemorySize, SMEM_P);
    cudaFuncSetAttribute((const void*)&k_mma<64, 128, true, false>,
                         cudaFuncAttributeMaxDynamicSharedMemorySize, SMEM_L);
    cudaFuncSetAttribute((const void*)&k_mma<512, 128, true, false>,
                         cudaFuncAttributeMaxDynamicSharedMemorySize, SMEM_L);

    // fork side streams off the (possibly capturing) default stream
    cudaStream_t sB, sC;
    cudaStreamCreateWithFlags(&sB, cudaStreamNonBlocking);
    cudaStreamCreateWithFlags(&sC, cudaStreamNonBlocking);
    cudaEvent_t evFork, evB, evC0, evC;
    cudaEventCreateWithFlags(&evFork, cudaEventDisableTiming);
    cudaEventCreateWithFlags(&evB,    cudaEventDisableTiming);
    cudaEventCreateWithFlags(&evC0,   cudaEventDisableTiming);
    cudaEventCreateWithFlags(&evC,    cudaEventDisableTiming);
    cudaEventRecord(evFork, 0);
    cudaStreamWaitEvent(sB, evFork, 0);
    cudaStreamWaitEvent(sC, evFork, 0);

    // main stream, launches 0..3 (index 3 = profiled proj0 mma, control)
    k_asplit<<<(M0 * 256 / 4 + 255) / 256, 256>>>(feat0, fhi, flo, M0 * 256);
    k_asplit<<<(M1 * 128 / 4 + 255) / 256, 256>>>(feat1, fhi + F0SZ, flo + F0SZ, M1 * 128);
    k_tsplit<<<dim3(2, 8),  dim3(32, 32)>>>(fc0w, wf0h, wf0l, 256, 64);
    k_mma<256, 64, false, true><<<dim3(1, 235), 256, SMEM_P>>>(
        fhi, flo, wf0h, wf0l, nullptr, hhi, hlo, fc0b,
        nullptr, nullptr, nullptr, nullptr, M0);

    // side stream B: CSR build
    k_zero_deg<<<(NN + 255) / 256, 256, 0, sB>>>();
    k_count<<<(E + 255) / 256, 256, 0, sB>>>(dst, E);
    k_scan1<<<NBLK, 256, 0, sB>>>();
    k_scan2<<<1, 256, 0, sB>>>();
    k_scan3<<<NBLK, 256, 0, sB>>>();
    k_scatter<<<(E + 255) / 256, 256, 0, sB>>>(src, dst, E);
    cudaEventRecord(evB, sB);

    // side stream C: el/er zero + W0 split (evC0), then W1 split (evC)
    k_zero_el<<<(NN * HEADS + 255) / 256, 256, 0, sC>>>();
    k_tsplit<<<dim3(16, 2),  dim3(32, 32), 0, sC>>>(W0, w0th, w0tl, 64, 512);
    cudaEventRecord(evC0, sC);
    k_tsplit<<<dim3(16, 16), dim3(32, 32), 0, sC>>>(W1, w1th, w1tl, 512, 512);
    cudaEventRecord(evC, sC);

    // main stream continues: proj1
    k_tsplit<<<dim3(2, 4), dim3(32, 32)>>>(fc1w, wf1h, wf1l, 128, 64);
    k_mma<128, 64, false, true><<<dim3(1, 157), 256, SMEM_P>>>(
        fhi + F0SZ, flo + F0SZ, wf1h, wf1l, nullptr,
        hhi + (size_t)M0 * 64, hlo + (size_t)M0 * 64, fc1b,
        nullptr, nullptr, nullptr, nullptr, M1);

    // join C0 (W0 split + zeros) before layer-0 mma
    cudaStreamWaitEvent(0, evC0, 0);
    k_mma<64, 128, true, false><<<dim3(4, 391), 256, SMEM_L>>>(
        hhi, hlo, w0th, w0tl, bufA, nullptr, nullptr, nullptr,
        al0, ar0, elA, erA, NN);

    // join B (CSR) before attention
    cudaStreamWaitEvent(0, evB, 0);
    k_attn<<<NN, dim3(32, HEADS)>>>(bufA, b0, elA, erA, ahi, alo);

    // join C (W1 split) before layer-1 mma
    cudaStreamWaitEvent(0, evC, 0);
    k_mma<512, 128, true, false><<<dim3(4, 391), 256, SMEM_L>>>(
        ahi, alo, w1th, w1tl, bufA, nullptr, nullptr, nullptr,
        al1, ar1, elB, erB, NN);
    k_attn<<<NN, dim3(32, HEADS)>>>(bufA, b1, elB, erB, ahi, alo);

    // layer 2
    k_gemm_n10<<<(NN + 7) / 8, 256>>>(ahi, alo, W2, bufB, al2, ar2, elA, erA, NN);
    k_agg10<<<NN, 32>>>(bufB, b2, elA, erA, outp);

    cudaEventDestroy(evFork);
    cudaEventDestroy(evB);
    cudaEventDestroy(evC0);
    cudaEventDestroy(evC);
    cudaStreamDestroy(sB);
    cudaStreamDestroy(sC);

    (void)n_in; (void)out_size;
}

// round 15
// speedup vs baseline: 1.1051x; 1.1051x over previous
#include <cuda_runtime.h>
#include <cuda_fp16.h>
#include <math.h>
#include <stdint.h>

#define NN 50000
#define NE 500000
#define HID 64
#define HEADS 8
#define NCLS 10
#define MPAD 50048            // 391 * 128
#define F0ROWS 30080          // 235*128
#define F1ROWS 20096          // 157*128
#define F0SZ (F0ROWS * 256)
#define FSZ  (F0SZ + F1ROWS * 128)
#define NBLK 196              // scan blocks: 196*256 = 50176 >= NN

// ---------------- scratch -----------------------------------------------
__device__ float g_bufA[(size_t)NN * 512];
__device__ float g_bufB[(size_t)NN * 16];
__device__ float g_elA[NN * HEADS];
__device__ float g_erA[NN * HEADS];
__device__ float g_elB[NN * HEADS];
__device__ float g_erB[NN * HEADS];
__device__ int   g_deg[NN];
__device__ int   g_rowptr[NN + 1];
__device__ int   g_cursor[NN];
__device__ int   g_csrsrc[NE];
__device__ int   g_blksum[256];
__device__ int   g_blkoff[256];
__device__ __half g_f_hi[FSZ];
__device__ __half g_f_lo[FSZ];
__device__ __half g_h_hi[(size_t)MPAD * 64];
__device__ __half g_h_lo[(size_t)MPAD * 64];
__device__ __half g_a_hi[(size_t)MPAD * 512];
__device__ __half g_a_lo[(size_t)MPAD * 512];
__device__ __half g_wf0_hi[64 * 256], g_wf0_lo[64 * 256];
__device__ __half g_wf1_hi[64 * 128], g_wf1_lo[64 * 128];
__device__ __half g_w0t_hi[512 * 64], g_w0t_lo[512 * 64];
__device__ __half g_w1t_hi[512 * 512], g_w1t_lo[512 * 512];

// ---------------- PTX helpers --------------------------------------------
__device__ __forceinline__ uint32_t smem_u32(const void* p) {
    uint32_t a;
    asm("{ .reg .u64 t; cvta.to.shared.u64 t, %1; cvt.u32.u64 %0, t; }" : "=r"(a) : "l"(p));
    return a;
}
__device__ __forceinline__ void cp_async16(uint32_t s, const void* g) {
    asm volatile("cp.async.cg.shared.global [%0], [%1], 16;" :: "r"(s), "l"(g));
}
#define CP_COMMIT() asm volatile("cp.async.commit_group;" ::: "memory")

__device__ __forceinline__ void ldsm_x4(uint32_t& r0, uint32_t& r1, uint32_t& r2, uint32_t& r3,
                                        uint32_t addr) {
    asm volatile("ldmatrix.sync.aligned.m8n8.x4.shared.b16 {%0,%1,%2,%3}, [%4];"
                 : "=r"(r0), "=r"(r1), "=r"(r2), "=r"(r3) : "r"(addr));
}
__device__ __forceinline__ void mma_f16(float* d, const uint32_t* a, const uint32_t* b) {
    asm volatile(
        "mma.sync.aligned.m16n8k16.row.col.f32.f16.f16.f32 "
        "{%0,%1,%2,%3}, {%4,%5,%6,%7}, {%8,%9}, {%0,%1,%2,%3};"
        : "+f"(d[0]), "+f"(d[1]), "+f"(d[2]), "+f"(d[3])
        : "r"(a[0]), "r"(a[1]), "r"(a[2]), "r"(a[3]), "r"(b[0]), "r"(b[1]));
}

// ---------------- graph preprocessing ---------------------------------------
__global__ void k_zero_deg() {
    int i = blockIdx.x * blockDim.x + threadIdx.x;
    if (i < NN) g_deg[i] = 0;
}
__global__ void k_zero_el() {
    int i = blockIdx.x * blockDim.x + threadIdx.x;
    if (i < NN * HEADS) {
        g_elA[i] = 0.f; g_erA[i] = 0.f;
        g_elB[i] = 0.f; g_erB[i] = 0.f;
    }
}
__global__ void k_count(const int* __restrict__ dst, int E) {
    int e = blockIdx.x * blockDim.x + threadIdx.x;
    if (e < E) atomicAdd(&g_deg[dst[e]], 1);
}
__global__ void k_scan1() {
    __shared__ int sh[256];
    int b = blockIdx.x, t = threadIdx.x;
    int i = b * 256 + t;
    int v = (i < NN) ? g_deg[i] : 0;
    sh[t] = v;
    __syncthreads();
#pragma unroll
    for (int off = 1; off < 256; off <<= 1) {
        int x = (t >= off) ? sh[t - off] : 0;
        __syncthreads();
        sh[t] += x;
        __syncthreads();
    }
    if (i < NN) g_rowptr[i] = sh[t] - v;
    if (t == 255) g_blksum[b] = sh[255];
}
__global__ void k_scan2() {
    __shared__ int sh[256];
    int t = threadIdx.x;
    int v = (t < NBLK) ? g_blksum[t] : 0;
    sh[t] = v;
    __syncthreads();
#pragma unroll
    for (int off = 1; off < 256; off <<= 1) {
        int x = (t >= off) ? sh[t - off] : 0;
        __syncthreads();
        sh[t] += x;
        __syncthreads();
    }
    if (t < NBLK) g_blkoff[t] = sh[t] - v;
    if (t == 255) g_rowptr[NN] = sh[255];
}
__global__ void k_scan3() {
    int i = blockIdx.x * blockDim.x + threadIdx.x;
    if (i < NN) {
        int r = g_rowptr[i] + g_blkoff[i >> 8];
        g_rowptr[i] = r;
        g_cursor[i] = r;
    }
}
__global__ void k_scatter(const int* __restrict__ src, const int* __restrict__ dst, int E) {
    int e = blockIdx.x * blockDim.x + threadIdx.x;
    if (e < E) {
        int pos = atomicAdd(&g_cursor[dst[e]], 1);
        g_csrsrc[pos] = src[e];
    }
}

// ---------------- weight transpose + fp16 split -----------------------------
__global__ void k_tsplit(const float* __restrict__ W, __half* __restrict__ Thi,
                         __half* __restrict__ Tlo, int K, int N)
{
    __shared__ float s[32][33];
    int tx = threadIdx.x, ty = threadIdx.y;
    int k = blockIdx.y * 32 + ty, n = blockIdx.x * 32 + tx;
    s[ty][tx] = W[(size_t)k * N + n];
    __syncthreads();
    int n2 = blockIdx.x * 32 + ty, k2 = blockIdx.y * 32 + tx;
    float v = s[tx][ty];
    __half h = __float2half_rn(v);
    Thi[(size_t)n2 * K + k2] = h;
    Tlo[(size_t)n2 * K + k2] = __float2half_rn(v - __half2float(h));
}

__global__ void k_asplit(const float* __restrict__ A, __half* __restrict__ hi,
                         __half* __restrict__ lo, int count)
{
    int i = (blockIdx.x * blockDim.x + threadIdx.x) * 4;
    if (i >= count) return;
    float4 v = *reinterpret_cast<const float4*>(A + i);
    __half2 h0, h1, l0, l1;
    h0.x = __float2half_rn(v.x); h0.y = __float2half_rn(v.y);
    h1.x = __float2half_rn(v.z); h1.y = __float2half_rn(v.w);
    l0.x = __float2half_rn(v.x - __half2float(h0.x));
    l0.y = __float2half_rn(v.y - __half2float(h0.y));
    l1.x = __float2half_rn(v.z - __half2float(h1.x));
    l1.y = __float2half_rn(v.w - __half2float(h1.y));
    *reinterpret_cast<__half2*>(hi + i) = h0;
    *reinterpret_cast<__half2*>(hi + i + 2) = h1;
    *reinterpret_cast<__half2*>(lo + i) = l0;
    *reinterpret_cast<__half2*>(lo + i + 2) = l1;
}

// ---------------- fp16 split mma GEMM ----------------------------------------
// NPROD=3: ah*bh + ah*bl + al*bh (projections, ~exact)
// NPROD=2: ah*bh + al*bh (layers; B single fp16, error = weight rounding)
// 4-stage cp.async pipeline; BUFB = 18432 for all variants.
#define ROWB 48
#define TILEB (128 * ROWB)
#define STG 4
template <int KDIM, int BN, bool FUSE, bool SPLIT_OUT, int NPROD>
__global__ __launch_bounds__(256) void k_mma(
    const __half* __restrict__ Ahi, const __half* __restrict__ Alo,
    const __half* __restrict__ Bhi, const __half* __restrict__ Blo,
    float* __restrict__ C,
    __half* __restrict__ Ohi, __half* __restrict__ Olo,
    const float* __restrict__ bias,
    const float* __restrict__ al, const float* __restrict__ ar,
    float* __restrict__ el, float* __restrict__ er,
    int M)
{
    constexpr int NCH = KDIM / 16;
    constexpr int MI = (BN == 128) ? 4 : 2;
    constexpr int BTILE = BN * ROWB;
    constexpr int BUFB = 2 * TILEB + (NPROD - 1) * BTILE;
    extern __shared__ char smem[];
    uint32_t sb = smem_u32(smem);

    const int tid = threadIdx.x;
    const int wid = tid >> 5, lane = tid & 31;
    const int bm = blockIdx.y * 128;
    const int bn = blockIdx.x * BN;
    const int wm = (BN == 128) ? (wid & 1) * 64 : (wid & 3) * 32;
    const int wn = (BN == 128) ? (wid >> 1) * 32 : (wid >> 2) * 32;

    const int lrow = tid >> 1, lhalf = tid & 1;
    const bool bOK = (BN == 128) || (tid < 128);
    const __half* gAh = Ahi + (size_t)(bm + lrow) * KDIM + lhalf * 8;
    const __half* gAl = Alo + (size_t)(bm + lrow) * KDIM + lhalf * 8;
    const int brow = bOK ? lrow : 0;
    const __half* gBh = Bhi + (size_t)(bn + brow) * KDIM + lhalf * 8;
    const __half* gBl = (NPROD == 3) ? (Blo + (size_t)(bn + brow) * KDIM + lhalf * 8) : gBh;
    const uint32_t sdst = lrow * ROWB + lhalf * 16;
    const uint32_t sdstB = brow * ROWB + lhalf * 16;

    auto load_chunk = [&](int c) {
        uint32_t base = sb + (c % STG) * BUFB;
        int k0 = c * 16;
        cp_async16(base + sdst,         gAh + k0);
        cp_async16(base + TILEB + sdst, gAl + k0);
        if (bOK) {
            cp_async16(base + 2 * TILEB + sdstB, gBh + k0);
            if (NPROD == 3)
                cp_async16(base + 2 * TILEB + BTILE + sdstB, gBl + k0);
        }
    };

    float acc[MI][4][4];
#pragma unroll
    for (int i = 0; i < MI; i++)
#pragma unroll
        for (int j = 0; j < 4; j++)
#pragma unroll
            for (int k = 0; k < 4; k++) acc[i][j][k] = 0.f;

#pragma unroll
    for (int c = 0; c < STG - 1 && c < NCH; c++) {
        load_chunk(c);
        CP_COMMIT();
    }

    const uint32_t a_off = (wm + (lane & 15)) * ROWB + (lane >> 4) * 16;
    const uint32_t b_off = (wn + (lane & 7) + ((lane >> 4) << 3)) * ROWB + (((lane >> 3) & 1) * 16);

    for (int c = 0; c < NCH; c++) {
        const uint32_t base = sb + (c % STG) * BUFB;
        asm volatile("cp.async.wait_group %0;" :: "n"(STG - 2));
        __syncthreads();

        if (c + STG - 1 < NCH) load_chunk(c + STG - 1);
        CP_COMMIT();

        uint32_t ahi[MI][4], alo[MI][4], bhi[4][2], blo[4][2];
#pragma unroll
        for (int mi = 0; mi < MI; mi++)
            ldsm_x4(ahi[mi][0], ahi[mi][1], ahi[mi][2], ahi[mi][3],
                    base + mi * 16 * ROWB + a_off);
#pragma unroll
        for (int p = 0; p < 2; p++) {
            uint32_t r0, r1, r2, r3;
            ldsm_x4(r0, r1, r2, r3, base + 2 * TILEB + p * 16 * ROWB + b_off);
            bhi[p * 2][0] = r0; bhi[p * 2][1] = r1;
            bhi[p * 2 + 1][0] = r2; bhi[p * 2 + 1][1] = r3;
        }
#pragma unroll
        for (int mi = 0; mi < MI; mi++)
            ldsm_x4(alo[mi][0], alo[mi][1], alo[mi][2], alo[mi][3],
                    base + TILEB + mi * 16 * ROWB + a_off);
        if (NPROD == 3) {
#pragma unroll
            for (int p = 0; p < 2; p++) {
                uint32_t r0, r1, r2, r3;
                ldsm_x4(r0, r1, r2, r3, base + 2 * TILEB + BTILE + p * 16 * ROWB + b_off);
                blo[p * 2][0] = r0; blo[p * 2][1] = r1;
                blo[p * 2 + 1][0] = r2; blo[p * 2 + 1][1] = r3;
            }
        }

        // dependency-free passes
#pragma unroll
        for (int mi = 0; mi < MI; mi++)
#pragma unroll
            for (int nb = 0; nb < 4; nb++)
                mma_f16(acc[mi][nb], ahi[mi], bhi[nb]);
#pragma unroll
        for (int mi = 0; mi < MI; mi++)
#pragma unroll
            for (int nb = 0; nb < 4; nb++)
                mma_f16(acc[mi][nb], alo[mi], bhi[nb]);
        if (NPROD == 3) {
#pragma unroll
            for (int mi = 0; mi < MI; mi++)
#pragma unroll
                for (int nb = 0; nb < 4; nb++)
                    mma_f16(acc[mi][nb], ahi[mi], blo[nb]);
        }
    }

    const int g = lane >> 2, t = lane & 3;

    if (SPLIT_OUT) {
#pragma unroll
        for (int mi = 0; mi < MI; mi++) {
            int r0 = bm + wm + mi * 16 + g;
            int r1 = r0 + 8;
#pragma unroll
            for (int nb = 0; nb < 4; nb++) {
                int col = wn + nb * 8 + 2 * t;
                float b0 = bias[col], b1 = bias[col + 1];
#pragma unroll
                for (int rr = 0; rr < 2; rr++) {
                    int r = rr ? r1 : r0;
                    if (r < M) {
                        float v0 = acc[mi][nb][rr * 2 + 0] + b0;
                        float v1 = acc[mi][nb][rr * 2 + 1] + b1;
                        __half2 h2, l2;
                        h2.x = __float2half_rn(v0); h2.y = __float2half_rn(v1);
                        l2.x = __float2half_rn(v0 - __half2float(h2.x));
                        l2.y = __float2half_rn(v1 - __half2float(h2.y));
                        *reinterpret_cast<__half2*>(Ohi + (size_t)r * BN + col) = h2;
                        *reinterpret_cast<__half2*>(Olo + (size_t)r * BN + col) = l2;
                    }
                }
            }
        }
    } else {
#pragma unroll
        for (int mi = 0; mi < MI; mi++) {
            int r0 = bm + wm + mi * 16 + g;
            int r1 = r0 + 8;
#pragma unroll
            for (int nb = 0; nb < 4; nb++) {
                int col = bn + wn + nb * 8 + 2 * t;
                if (r0 < M)
                    *reinterpret_cast<float2*>(C + (size_t)r0 * 512 + col) =
                        make_float2(acc[mi][nb][0], acc[mi][nb][1]);
                if (r1 < M)
                    *reinterpret_cast<float2*>(C + (size_t)r1 * 512 + col) =
                        make_float2(acc[mi][nb][2], acc[mi][nb][3]);
            }
        }
        if (FUSE) {
            int hh = (bn + wn) >> 6;
            float av[4][2], rv[4][2];
#pragma unroll
            for (int nb = 0; nb < 4; nb++)
#pragma unroll
                for (int k = 0; k < 2; k++) {
                    int colh = (wn & 63) + nb * 8 + 2 * t + k;
                    av[nb][k] = al[hh * 64 + colh];
                    rv[nb][k] = ar[hh * 64 + colh];
                }
#pragma unroll
            for (int mi = 0; mi < MI; mi++) {
                float pel0 = 0.f, per0 = 0.f, pel1 = 0.f, per1 = 0.f;
#pragma unroll
                for (int nb = 0; nb < 4; nb++) {
                    pel0 += acc[mi][nb][0] * av[nb][0] + acc[mi][nb][1] * av[nb][1];
                    per0 += acc[mi][nb][0] * rv[nb][0] + acc[mi][nb][1] * rv[nb][1];
                    pel1 += acc[mi][nb][2] * av[nb][0] + acc[mi][nb][3] * av[nb][1];
                    per1 += acc[mi][nb][2] * rv[nb][0] + acc[mi][nb][3] * rv[nb][1];
                }
#pragma unroll
                for (int off = 1; off <= 2; off <<= 1) {
                    pel0 += __shfl_xor_sync(0xffffffffu, pel0, off);
                    per0 += __shfl_xor_sync(0xffffffffu, per0, off);
                    pel1 += __shfl_xor_sync(0xffffffffu, pel1, off);
                    per1 += __shfl_xor_sync(0xffffffffu, per1, off);
                }
                if (t == 0) {
                    int r0 = bm + wm + mi * 16 + g;
                    int r1 = r0 + 8;
                    if (r0 < M) {
                        atomicAdd(&el[r0 * HEADS + hh], pel0);
                        atomicAdd(&er[r0 * HEADS + hh], per0);
                    }
                    if (r1 < M) {
                        atomicAdd(&el[r1 * HEADS + hh], pel1);
                        atomicAdd(&er[r1 * HEADS + hh], per1);
                    }
                }
            }
        }
    }
}

// ---------------- fused edge-softmax + aggregation ---------------------------
__device__ __forceinline__ float lrelu(float x) { return x > 0.f ? x : 0.2f * x; }

__global__ void k_attn(const float* __restrict__ feat, const float* __restrict__ bias,
                       const float* __restrict__ el, const float* __restrict__ er,
                       __half* __restrict__ Ohi, __half* __restrict__ Olo)
{
    int n = blockIdx.x;
    int h = threadIdx.y;
    int lane = threadIdx.x;
    int start = g_rowptr[n], end = g_rowptr[n + 1];
    int deg = end - start;
    float er_h = er[n * HEADS + h];

    float ax = 0.f, ay = 0.f;

    if (deg <= 32) {
        int s = 0;
        float e = -INFINITY;
        if (lane < deg) {
            s = g_csrsrc[start + lane];
            e = lrelu(el[s * HEADS + h] + er_h);
        }
        float m = e;
#pragma unroll
        for (int o = 16; o; o >>= 1) m = fmaxf(m, __shfl_xor_sync(0xffffffffu, m, o));
        float ws = (lane < deg) ? __expf(e - m) : 0.f;
        float dsum = ws;
#pragma unroll
        for (int o = 16; o; o >>= 1) dsum += __shfl_xor_sync(0xffffffffu, dsum, o);
        float w = ws / fmaxf(dsum, 1e-9f);

        int j = 0;
        for (; j + 4 <= deg; j += 4) {
            int   s0 = __shfl_sync(0xffffffffu, s, j + 0);
            int   s1 = __shfl_sync(0xffffffffu, s, j + 1);
            int   s2 = __shfl_sync(0xffffffffu, s, j + 2);
            int   s3 = __shfl_sync(0xffffffffu, s, j + 3);
            float w0 = __shfl_sync(0xffffffffu, w, j + 0);
            float w1 = __shfl_sync(0xffffffffu, w, j + 1);
            float w2 = __shfl_sync(0xffffffffu, w, j + 2);
            float w3 = __shfl_sync(0xffffffffu, w, j + 3);
            float2 v0 = *reinterpret_cast<const float2*>(feat + (size_t)s0 * 512 + h * 64 + lane * 2);
            float2 v1 = *reinterpret_cast<const float2*>(feat + (size_t)s1 * 512 + h * 64 + lane * 2);
            float2 v2 = *reinterpret_cast<const float2*>(feat + (size_t)s2 * 512 + h * 64 + lane * 2);
            float2 v3 = *reinterpret_cast<const float2*>(feat + (size_t)s3 * 512 + h * 64 + lane * 2);
            ax += w0 * v0.x + w1 * v1.x + w2 * v2.x + w3 * v3.x;
            ay += w0 * v0.y + w1 * v1.y + w2 * v2.y + w3 * v3.y;
        }
        for (; j < deg; j++) {
            int   sj = __shfl_sync(0xffffffffu, s, j);
            float wj = __shfl_sync(0xffffffffu, w, j);
            float2 v = *reinterpret_cast<const float2*>(feat + (size_t)sj * 512 + h * 64 + lane * 2);
            ax += wj * v.x; ay += wj * v.y;
        }
    } else {
        float m = -INFINITY;
        for (int j = start + lane; j < end; j += 32)
            m = fmaxf(m, lrelu(el[g_csrsrc[j] * HEADS + h] + er_h));
#pragma unroll
        for (int o = 16; o; o >>= 1) m = fmaxf(m, __shfl_xor_sync(0xffffffffu, m, o));

        float dsum = 0.f;
        for (int j = start + lane; j < end; j += 32)
            dsum += __expf(lrelu(el[g_csrsrc[j] * HEADS + h] + er_h) - m);
#pragma unroll
        for (int o = 16; o; o >>= 1) dsum += __shfl_xor_sync(0xffffffffu, dsum, o);
        float inv = 1.0f / fmaxf(dsum, 1e-9f);

        for (int j0 = start; j0 < end; j0 += 32) {
            int jmax = end - j0; if (jmax > 32) jmax = 32;
            int s_l = 0; float w_l = 0.f;
            if (lane < jmax) {
                s_l = g_csrsrc[j0 + lane];
                w_l = __expf(lrelu(el[s_l * HEADS + h] + er_h) - m) * inv;
            }
            for (int jj = 0; jj < jmax; jj++) {
                int   sj = __shfl_sync(0xffffffffu, s_l, jj);
                float wj = __shfl_sync(0xffffffffu, w_l, jj);
                float2 v = *reinterpret_cast<const float2*>(feat + (size_t)sj * 512 + h * 64 + lane * 2);
                ax += wj * v.x; ay += wj * v.y;
            }
        }
    }

    float vx = ax + bias[h * 64 + lane * 2];
    float vy = ay + bias[h * 64 + lane * 2 + 1];
    vx = vx > 0.f ? vx : (__expf(vx) - 1.f);
    vy = vy > 0.f ? vy : (__expf(vy) - 1.f);
    __half2 h2, l2;
    h2.x = __float2half_rn(vx); h2.y = __float2half_rn(vy);
    l2.x = __float2half_rn(vx - __half2float(h2.x));
    l2.y = __float2half_rn(vy - __half2float(h2.y));
    size_t o = (size_t)n * 512 + h * 64 + lane * 2;
    *reinterpret_cast<__half2*>(Ohi + o) = h2;
    *reinterpret_cast<__half2*>(Olo + o) = l2;
}

// ---------------- skinny GEMM + fused el/er (layer 2) ------------------------
__global__ __launch_bounds__(256) void k_gemm_n10(
    const __half* __restrict__ Ahi, const __half* __restrict__ Alo,
    const float* __restrict__ B, float* __restrict__ C,
    const float* __restrict__ al2, const float* __restrict__ ar2,
    float* __restrict__ el, float* __restrict__ er, int M)
{
    __shared__ float Bs[512 * 10];
    int tid = threadIdx.x;
    for (int i = tid; i < 512 * 10; i += 256) Bs[i] = B[i];
    __syncthreads();
    int warp = tid >> 5, lane = tid & 31;
    int row = blockIdx.x * 8 + warp;
    if (row >= M) return;
    float acc[10];
#pragma unroll
    for (int c = 0; c < 10; c++) acc[c] = 0.0f;
#pragma unroll
    for (int i = 0; i < 8; i++) {
        int k = lane * 2 + i * 64;
        __half2 h2 = *reinterpret_cast<const __half2*>(Ahi + (size_t)row * 512 + k);
        __half2 l2 = *reinterpret_cast<const __half2*>(Alo + (size_t)row * 512 + k);
        float a0 = __half2float(h2.x) + __half2float(l2.x);
        float a1 = __half2float(h2.y) + __half2float(l2.y);
#pragma unroll
        for (int c = 0; c < 10; c++)
            acc[c] += a0 * Bs[k * 10 + c] + a1 * Bs[(k + 1) * 10 + c];
    }
#pragma unroll
    for (int c = 0; c < 10; c++)
#pragma unroll
        for (int o = 16; o; o >>= 1) acc[c] += __shfl_xor_sync(0xffffffffu, acc[c], o);
    if (lane == 0) {
        float e_l = 0.f, e_r = 0.f;
#pragma unroll
        for (int c = 0; c < 10; c++) {
            C[(size_t)row * 10 + c] = acc[c];
            e_l += acc[c] * al2[c];
            e_r += acc[c] * ar2[c];
        }
        el[row] = e_l;
        er[row] = e_r;
    }
}

// ---------------- layer-2 agg (D=10, f32 out) --------------------------------
__global__ void k_agg10(const float* __restrict__ feat, const float* __restrict__ bias,
                        const float* __restrict__ el, const float* __restrict__ er,
                        float* __restrict__ out)
{
    int n = blockIdx.x;
    int lane = threadIdx.x;
    int start = g_rowptr[n], end = g_rowptr[n + 1];
    float er_h = er[n];

    float m = -INFINITY;
    for (int j = start + lane; j < end; j += 32)
        m = fmaxf(m, lrelu(el[g_csrsrc[j]] + er_h));
#pragma unroll
    for (int o = 16; o; o >>= 1) m = fmaxf(m, __shfl_xor_sync(0xffffffffu, m, o));

    float dsum = 0.f;
    for (int j = start + lane; j < end; j += 32)
        dsum += __expf(lrelu(el[g_csrsrc[j]] + er_h) - m);
#pragma unroll
    for (int o = 16; o; o >>= 1) dsum += __shfl_xor_sync(0xffffffffu, dsum, o);
    float inv = 1.0f / fmaxf(dsum, 1e-9f);

    float acc = 0.f;
    for (int j0 = start; j0 < end; j0 += 32) {
        int jmax = end - j0; if (jmax > 32) jmax = 32;
        int s_l = 0; float w_l = 0.f;
        if (lane < jmax) {
            s_l = g_csrsrc[j0 + lane];
            w_l = __expf(lrelu(el[s_l] + er_h) - m);
        }
        for (int jj = 0; jj < jmax; jj++) {
            int   s = __shfl_sync(0xffffffffu, s_l, jj);
            float w = __shfl_sync(0xffffffffu, w_l, jj);
            if (lane < NCLS) acc += w * feat[(size_t)s * NCLS + lane];
        }
    }
    if (lane < NCLS) out[(size_t)n * NCLS + lane] = acc * inv + bias[lane];
}

// ---------------- launcher ----------------------------------------------------
extern "C" void kernel_launch(void* const* d_in, const int* in_sizes, int n_in,
                              void* d_out, int out_size)
{
    const float* feat0 = (const float*)d_in[0];
    const float* feat1 = (const float*)d_in[1];
    const float* fc0w  = (const float*)d_in[2];
    const float* fc0b  = (const float*)d_in[3];
    const float* fc1w  = (const float*)d_in[4];
    const float* fc1b  = (const float*)d_in[5];
    const float* W0    = (const float*)d_in[6];
    const float* al0   = (const float*)d_in[7];
    const float* ar0   = (const float*)d_in[8];
    const float* b0    = (const float*)d_in[9];
    const float* W1    = (const float*)d_in[10];
    const float* al1   = (const float*)d_in[11];
    const float* ar1   = (const float*)d_in[12];
    const float* b1    = (const float*)d_in[13];
    const float* W2    = (const float*)d_in[14];
    const float* al2   = (const float*)d_in[15];
    const float* ar2   = (const float*)d_in[16];
    const float* b2    = (const float*)d_in[17];
    const int*   ei    = (const int*)d_in[18];

    const int E = in_sizes[18] / 2;
    const int M0 = in_sizes[0] / 256;   // 30000
    const int M1 = in_sizes[1] / 128;   // 20000
    const int* src = ei;
    const int* dst = ei + E;

    float *bufA, *bufB, *elA, *erA, *elB, *erB;
    __half *fhi, *flo, *hhi, *hlo, *ahi, *alo;
    __half *wf0h, *wf0l, *wf1h, *wf1l, *w0th, *w0tl, *w1th, *w1tl;
    cudaGetSymbolAddress((void**)&bufA, g_bufA);
    cudaGetSymbolAddress((void**)&bufB, g_bufB);
    cudaGetSymbolAddress((void**)&elA,  g_elA);
    cudaGetSymbolAddress((void**)&erA,  g_erA);
    cudaGetSymbolAddress((void**)&elB,  g_elB);
    cudaGetSymbolAddress((void**)&erB,  g_erB);
    cudaGetSymbolAddress((void**)&fhi,  g_f_hi);
    cudaGetSymbolAddress((void**)&flo,  g_f_lo);
    cudaGetSymbolAddress((void**)&hhi,  g_h_hi);
    cudaGetSymbolAddress((void**)&hlo,  g_h_lo);
    cudaGetSymbolAddress((void**)&ahi,  g_a_hi);
    cudaGetSymbolAddress((void**)&alo,  g_a_lo);
    cudaGetSymbolAddress((void**)&wf0h, g_wf0_hi);
    cudaGetSymbolAddress((void**)&wf0l, g_wf0_lo);
    cudaGetSymbolAddress((void**)&wf1h, g_wf1_hi);
    cudaGetSymbolAddress((void**)&wf1l, g_wf1_lo);
    cudaGetSymbolAddress((void**)&w0th, g_w0t_hi);
    cudaGetSymbolAddress((void**)&w0tl, g_w0t_lo);
    cudaGetSymbolAddress((void**)&w1th, g_w1t_hi);
    cudaGetSymbolAddress((void**)&w1tl, g_w1t_lo);

    float* outp = (float*)d_out;

    // all variants: BUFB = 18432, 4 stages
    constexpr int SMEM_MM = STG * 18432;   // 73728
    cudaFuncSetAttribute((const void*)&k_mma<256, 64, false, true, 3>,
                         cudaFuncAttributeMaxDynamicSharedMemorySize, SMEM_MM);
    cudaFuncSetAttribute((const void*)&k_mma<128, 64, false, true, 3>,
                         cudaFuncAttributeMaxDynamicSharedMemorySize, SMEM_MM);
    cudaFuncSetAttribute((const void*)&k_mma<64, 128, true, false, 2>,
                         cudaFuncAttributeMaxDynamicSharedMemorySize, SMEM_MM);
    cudaFuncSetAttribute((const void*)&k_mma<512, 128, true, false, 2>,
                         cudaFuncAttributeMaxDynamicSharedMemorySize, SMEM_MM);

    // fork side streams off the (possibly capturing) default stream
    cudaStream_t sB, sC;
    cudaStreamCreateWithFlags(&sB, cudaStreamNonBlocking);
    cudaStreamCreateWithFlags(&sC, cudaStreamNonBlocking);
    cudaEvent_t evFork, evB, evC0, evC;
    cudaEventCreateWithFlags(&evFork, cudaEventDisableTiming);
    cudaEventCreateWithFlags(&evB,    cudaEventDisableTiming);
    cudaEventCreateWithFlags(&evC0,   cudaEventDisableTiming);
    cudaEventCreateWithFlags(&evC,    cudaEventDisableTiming);
    cudaEventRecord(evFork, 0);
    cudaStreamWaitEvent(sB, evFork, 0);
    cudaStreamWaitEvent(sC, evFork, 0);

    // main stream, launches 0..3 (index 3 = profiled proj0 mma)
    k_asplit<<<(M0 * 256 / 4 + 255) / 256, 256>>>(feat0, fhi, flo, M0 * 256);
    k_asplit<<<(M1 * 128 / 4 + 255) / 256, 256>>>(feat1, fhi + F0SZ, flo + F0SZ, M1 * 128);
    k_tsplit<<<dim3(2, 8),  dim3(32, 32)>>>(fc0w, wf0h, wf0l, 256, 64);
    k_mma<256, 64, false, true, 3><<<dim3(1, 235), 256, SMEM_MM>>>(
        fhi, flo, wf0h, wf0l, nullptr, hhi, hlo, fc0b,
        nullptr, nullptr, nullptr, nullptr, M0);

    // side stream B: CSR build
    k_zero_deg<<<(NN + 255) / 256, 256, 0, sB>>>();
    k_count<<<(E + 255) / 256, 256, 0, sB>>>(dst, E);
    k_scan1<<<NBLK, 256, 0, sB>>>();
    k_scan2<<<1, 256, 0, sB>>>();
    k_scan3<<<NBLK, 256, 0, sB>>>();
    k_scatter<<<(E + 255) / 256, 256, 0, sB>>>(src, dst, E);
    cudaEventRecord(evB, sB);

    // side stream C: el/er zero + W0 split (evC0), then W1 split (evC)
    k_zero_el<<<(NN * HEADS + 255) / 256, 256, 0, sC>>>();
    k_tsplit<<<dim3(16, 2),  dim3(32, 32), 0, sC>>>(W0, w0th, w0tl, 64, 512);
    cudaEventRecord(evC0, sC);
    k_tsplit<<<dim3(16, 16), dim3(32, 32), 0, sC>>>(W1, w1th, w1tl, 512, 512);
    cudaEventRecord(evC, sC);

    // main stream continues: proj1
    k_tsplit<<<dim3(2, 4), dim3(32, 32)>>>(fc1w, wf1h, wf1l, 128, 64);
    k_mma<128, 64, false, true, 3><<<dim3(1, 157), 256, SMEM_MM>>>(
        fhi + F0SZ, flo + F0SZ, wf1h, wf1l, nullptr,
        hhi + (size_t)M0 * 64, hlo + (size_t)M0 * 64, fc1b,
        nullptr, nullptr, nullptr, nullptr, M1);

    // join C0 (W0 split + zeros) before layer-0 mma
    cudaStreamWaitEvent(0, evC0, 0);
    k_mma<64, 128, true, false, 2><<<dim3(4, 391), 256, SMEM_MM>>>(
        hhi, hlo, w0th, w0tl, bufA, nullptr, nullptr, nullptr,
        al0, ar0, elA, erA, NN);

    // join B (CSR) before attention
    cudaStreamWaitEvent(0, evB, 0);
    k_attn<<<NN, dim3(32, HEADS)>>>(bufA, b0, elA, erA, ahi, alo);

    // join C (W1 split) before layer-1 mma
    cudaStreamWaitEvent(0, evC, 0);
    k_mma<512, 128, true, false, 2><<<dim3(4, 391), 256, SMEM_MM>>>(
        ahi, alo, w1th, w1tl, bufA, nullptr, nullptr, nullptr,
        al1, ar1, elB, erB, NN);
    k_attn<<<NN, dim3(32, HEADS)>>>(bufA, b1, elB, erB, ahi, alo);

    // layer 2
    k_gemm_n10<<<(NN + 7) / 8, 256>>>(ahi, alo, W2, bufB, al2, ar2, elA, erA, NN);
    k_agg10<<<NN, 32>>>(bufB, b2, elA, erA, outp);

    cudaEventDestroy(evFork);
    cudaEventDestroy(evB);
    cudaEventDestroy(evC0);
    cudaEventDestroy(evC);
    cudaStreamDestroy(sB);
    cudaStreamDestroy(sC);

    (void)n_in; (void)out_size;
}

// round 17
// speedup vs baseline: 1.3626x; 1.2329x over previous
#include <cuda_runtime.h>
#include <cuda_fp16.h>
#include <math.h>
#include <stdint.h>

#define NN 50000
#define NE 500000
#define HID 64
#define HEADS 8
#define NCLS 10
#define MPAD 50048            // 391 * 128
#define F0ROWS 30080          // 235*128
#define F1ROWS 20096          // 157*128
#define F0SZ (F0ROWS * 256)
#define FSZ  (F0SZ + F1ROWS * 128)
#define NBLK 196              // scan blocks: 196*256 = 50176 >= NN

// ---------------- scratch -----------------------------------------------
__device__ float g_bufA[(size_t)NN * 512];
__device__ float g_bufB[(size_t)NN * 16];
__device__ float g_elA[NN * HEADS];
__device__ float g_erA[NN * HEADS];
__device__ float g_elB[NN * HEADS];
__device__ float g_erB[NN * HEADS];
__device__ int   g_deg[NN];
__device__ int   g_rowptr[NN + 1];
__device__ int   g_cursor[NN];
__device__ int   g_csrsrc[NE];
__device__ int   g_blksum[256];
__device__ int   g_blkoff[256];
__device__ __half g_f_hi[FSZ];
__device__ __half g_f_lo[FSZ];
__device__ __half g_h_hi[(size_t)MPAD * 64];
__device__ __half g_h_lo[(size_t)MPAD * 64];
__device__ __half g_a_hi[(size_t)MPAD * 512];
__device__ __half g_a_lo[(size_t)MPAD * 512];
__device__ __half g_wf0_hi[64 * 256], g_wf0_lo[64 * 256];
__device__ __half g_wf1_hi[64 * 128], g_wf1_lo[64 * 128];
__device__ __half g_w0t_hi[512 * 64], g_w0t_lo[512 * 64];
__device__ __half g_w1t_hi[512 * 512], g_w1t_lo[512 * 512];

// ---------------- PTX helpers --------------------------------------------
__device__ __forceinline__ uint32_t smem_u32(const void* p) {
    uint32_t a;
    asm("{ .reg .u64 t; cvta.to.shared.u64 t, %1; cvt.u32.u64 %0, t; }" : "=r"(a) : "l"(p));
    return a;
}
__device__ __forceinline__ void cp_async16(uint32_t s, const void* g) {
    asm volatile("cp.async.cg.shared.global [%0], [%1], 16;" :: "r"(s), "l"(g));
}
#define CP_COMMIT() asm volatile("cp.async.commit_group;" ::: "memory")

__device__ __forceinline__ void ldsm_x4(uint32_t& r0, uint32_t& r1, uint32_t& r2, uint32_t& r3,
                                        uint32_t addr) {
    asm volatile("ldmatrix.sync.aligned.m8n8.x4.shared.b16 {%0,%1,%2,%3}, [%4];"
                 : "=r"(r0), "=r"(r1), "=r"(r2), "=r"(r3) : "r"(addr));
}
__device__ __forceinline__ void mma_f16(float* d, const uint32_t* a, const uint32_t* b) {
    asm volatile(
        "mma.sync.aligned.m16n8k16.row.col.f32.f16.f16.f32 "
        "{%0,%1,%2,%3}, {%4,%5,%6,%7}, {%8,%9}, {%0,%1,%2,%3};"
        : "+f"(d[0]), "+f"(d[1]), "+f"(d[2]), "+f"(d[3])
        : "r"(a[0]), "r"(a[1]), "r"(a[2]), "r"(a[3]), "r"(b[0]), "r"(b[1]));
}

// ---------------- graph preprocessing ---------------------------------------
__global__ void k_zero_deg() {
    int i = blockIdx.x * blockDim.x + threadIdx.x;
    if (i < NN) g_deg[i] = 0;
}
__global__ void k_zero_el() {
    int i = blockIdx.x * blockDim.x + threadIdx.x;
    if (i < NN * HEADS) {
        g_elA[i] = 0.f; g_erA[i] = 0.f;
        g_elB[i] = 0.f; g_erB[i] = 0.f;
    }
}
__global__ void k_count(const int* __restrict__ dst, int E) {
    int e = blockIdx.x * blockDim.x + threadIdx.x;
    if (e < E) atomicAdd(&g_deg[dst[e]], 1);
}
__global__ void k_scan1() {
    __shared__ int sh[256];
    int b = blockIdx.x, t = threadIdx.x;
    int i = b * 256 + t;
    int v = (i < NN) ? g_deg[i] : 0;
    sh[t] = v;
    __syncthreads();
#pragma unroll
    for (int off = 1; off < 256; off <<= 1) {
        int x = (t >= off) ? sh[t - off] : 0;
        __syncthreads();
        sh[t] += x;
        __syncthreads();
    }
    if (i < NN) g_rowptr[i] = sh[t] - v;
    if (t == 255) g_blksum[b] = sh[255];
}
__global__ void k_scan2() {
    __shared__ int sh[256];
    int t = threadIdx.x;
    int v = (t < NBLK) ? g_blksum[t] : 0;
    sh[t] = v;
    __syncthreads();
#pragma unroll
    for (int off = 1; off < 256; off <<= 1) {
        int x = (t >= off) ? sh[t - off] : 0;
        __syncthreads();
        sh[t] += x;
        __syncthreads();
    }
    if (t < NBLK) g_blkoff[t] = sh[t] - v;
    if (t == 255) g_rowptr[NN] = sh[255];
}
__global__ void k_scan3() {
    int i = blockIdx.x * blockDim.x + threadIdx.x;
    if (i < NN) {
        int r = g_rowptr[i] + g_blkoff[i >> 8];
        g_rowptr[i] = r;
        g_cursor[i] = r;
    }
}
__global__ void k_scatter(const int* __restrict__ src, const int* __restrict__ dst, int E) {
    int e = blockIdx.x * blockDim.x + threadIdx.x;
    if (e < E) {
        int pos = atomicAdd(&g_cursor[dst[e]], 1);
        g_csrsrc[pos] = src[e];
    }
}

// ---------------- weight transpose + fp16 split -----------------------------
__global__ void k_tsplit(const float* __restrict__ W, __half* __restrict__ Thi,
                         __half* __restrict__ Tlo, int K, int N)
{
    __shared__ float s[32][33];
    int tx = threadIdx.x, ty = threadIdx.y;
    int k = blockIdx.y * 32 + ty, n = blockIdx.x * 32 + tx;
    s[ty][tx] = W[(size_t)k * N + n];
    __syncthreads();
    int n2 = blockIdx.x * 32 + ty, k2 = blockIdx.y * 32 + tx;
    float v = s[tx][ty];
    __half h = __float2half_rn(v);
    Thi[(size_t)n2 * K + k2] = h;
    Tlo[(size_t)n2 * K + k2] = __float2half_rn(v - __half2float(h));
}

__global__ void k_asplit(const float* __restrict__ A, __half* __restrict__ hi,
                         __half* __restrict__ lo, int count)
{
    int i = (blockIdx.x * blockDim.x + threadIdx.x) * 4;
    if (i >= count) return;
    float4 v = *reinterpret_cast<const float4*>(A + i);
    __half2 h0, h1, l0, l1;
    h0.x = __float2half_rn(v.x); h0.y = __float2half_rn(v.y);
    h1.x = __float2half_rn(v.z); h1.y = __float2half_rn(v.w);
    l0.x = __float2half_rn(v.x - __half2float(h0.x));
    l0.y = __float2half_rn(v.y - __half2float(h0.y));
    l1.x = __float2half_rn(v.z - __half2float(h1.x));
    l1.y = __float2half_rn(v.w - __half2float(h1.y));
    *reinterpret_cast<__half2*>(hi + i) = h0;
    *reinterpret_cast<__half2*>(hi + i + 2) = h1;
    *reinterpret_cast<__half2*>(lo + i) = l0;
    *reinterpret_cast<__half2*>(lo + i + 2) = l1;
}

// ---------------- fp16 split mma GEMM ----------------------------------------
// NPROD=3: ah*bh + ah*bl + al*bh (projections, ~exact)
// NPROD=2: ah*bh + al*bh (layers; B single fp16)
#define ROWB 48
#define TILEB (128 * ROWB)
#define STG 4
template <int KDIM, int BN, bool FUSE, bool SPLIT_OUT, int NPROD>
__global__ __launch_bounds__(256) void k_mma(
    const __half* __restrict__ Ahi, const __half* __restrict__ Alo,
    const __half* __restrict__ Bhi, const __half* __restrict__ Blo,
    float* __restrict__ C,
    __half* __restrict__ Ohi, __half* __restrict__ Olo,
    const float* __restrict__ bias,
    const float* __restrict__ al, const float* __restrict__ ar,
    float* __restrict__ el, float* __restrict__ er,
    int M)
{
    constexpr int NCH = KDIM / 16;
    constexpr int MI = (BN == 128) ? 4 : 2;
    constexpr int BTILE = BN * ROWB;
    constexpr int BUFB = 2 * TILEB + (NPROD - 1) * BTILE;
    extern __shared__ char smem[];
    uint32_t sb = smem_u32(smem);

    const int tid = threadIdx.x;
    const int wid = tid >> 5, lane = tid & 31;
    const int bm = blockIdx.y * 128;
    const int bn = blockIdx.x * BN;
    const int wm = (BN == 128) ? (wid & 1) * 64 : (wid & 3) * 32;
    const int wn = (BN == 128) ? (wid >> 1) * 32 : (wid >> 2) * 32;

    const int lrow = tid >> 1, lhalf = tid & 1;
    const bool bOK = (BN == 128) || (tid < 128);
    const __half* gAh = Ahi + (size_t)(bm + lrow) * KDIM + lhalf * 8;
    const __half* gAl = Alo + (size_t)(bm + lrow) * KDIM + lhalf * 8;
    const int brow = bOK ? lrow : 0;
    const __half* gBh = Bhi + (size_t)(bn + brow) * KDIM + lhalf * 8;
    const __half* gBl = (NPROD == 3) ? (Blo + (size_t)(bn + brow) * KDIM + lhalf * 8) : gBh;
    const uint32_t sdst = lrow * ROWB + lhalf * 16;
    const uint32_t sdstB = brow * ROWB + lhalf * 16;

    auto load_chunk = [&](int c) {
        uint32_t base = sb + (c % STG) * BUFB;
        int k0 = c * 16;
        cp_async16(base + sdst,         gAh + k0);
        cp_async16(base + TILEB + sdst, gAl + k0);
        if (bOK) {
            cp_async16(base + 2 * TILEB + sdstB, gBh + k0);
            if (NPROD == 3)
                cp_async16(base + 2 * TILEB + BTILE + sdstB, gBl + k0);
        }
    };

    float acc[MI][4][4];
#pragma unroll
    for (int i = 0; i < MI; i++)
#pragma unroll
        for (int j = 0; j < 4; j++)
#pragma unroll
            for (int k = 0; k < 4; k++) acc[i][j][k] = 0.f;

#pragma unroll
    for (int c = 0; c < STG - 1 && c < NCH; c++) {
        load_chunk(c);
        CP_COMMIT();
    }

    const uint32_t a_off = (wm + (lane & 15)) * ROWB + (lane >> 4) * 16;
    const uint32_t b_off = (wn + (lane & 7) + ((lane >> 4) << 3)) * ROWB + (((lane >> 3) & 1) * 16);

    for (int c = 0; c < NCH; c++) {
        const uint32_t base = sb + (c % STG) * BUFB;
        asm volatile("cp.async.wait_group %0;" :: "n"(STG - 2));
        __syncthreads();

        if (c + STG - 1 < NCH) load_chunk(c + STG - 1);
        CP_COMMIT();

        uint32_t ahi[MI][4], alo[MI][4], bhi[4][2], blo[4][2];
#pragma unroll
        for (int mi = 0; mi < MI; mi++)
            ldsm_x4(ahi[mi][0], ahi[mi][1], ahi[mi][2], ahi[mi][3],
                    base + mi * 16 * ROWB + a_off);
#pragma unroll
        for (int p = 0; p < 2; p++) {
            uint32_t r0, r1, r2, r3;
            ldsm_x4(r0, r1, r2, r3, base + 2 * TILEB + p * 16 * ROWB + b_off);
            bhi[p * 2][0] = r0; bhi[p * 2][1] = r1;
            bhi[p * 2 + 1][0] = r2; bhi[p * 2 + 1][1] = r3;
        }
#pragma unroll
        for (int mi = 0; mi < MI; mi++)
            ldsm_x4(alo[mi][0], alo[mi][1], alo[mi][2], alo[mi][3],
                    base + TILEB + mi * 16 * ROWB + a_off);
        if (NPROD == 3) {
#pragma unroll
            for (int p = 0; p < 2; p++) {
                uint32_t r0, r1, r2, r3;
                ldsm_x4(r0, r1, r2, r3, base + 2 * TILEB + BTILE + p * 16 * ROWB + b_off);
                blo[p * 2][0] = r0; blo[p * 2][1] = r1;
                blo[p * 2 + 1][0] = r2; blo[p * 2 + 1][1] = r3;
            }
        }

#pragma unroll
        for (int mi = 0; mi < MI; mi++)
#pragma unroll
            for (int nb = 0; nb < 4; nb++)
                mma_f16(acc[mi][nb], ahi[mi], bhi[nb]);
#pragma unroll
        for (int mi = 0; mi < MI; mi++)
#pragma unroll
            for (int nb = 0; nb < 4; nb++)
                mma_f16(acc[mi][nb], alo[mi], bhi[nb]);
        if (NPROD == 3) {
#pragma unroll
            for (int mi = 0; mi < MI; mi++)
#pragma unroll
                for (int nb = 0; nb < 4; nb++)
                    mma_f16(acc[mi][nb], ahi[mi], blo[nb]);
        }
    }

    const int g = lane >> 2, t = lane & 3;

    if (SPLIT_OUT) {
#pragma unroll
        for (int mi = 0; mi < MI; mi++) {
            int r0 = bm + wm + mi * 16 + g;
            int r1 = r0 + 8;
#pragma unroll
            for (int nb = 0; nb < 4; nb++) {
                int col = wn + nb * 8 + 2 * t;
                float b0 = bias[col], b1 = bias[col + 1];
#pragma unroll
                for (int rr = 0; rr < 2; rr++) {
                    int r = rr ? r1 : r0;
                    if (r < M) {
                        float v0 = acc[mi][nb][rr * 2 + 0] + b0;
                        float v1 = acc[mi][nb][rr * 2 + 1] + b1;
                        __half2 h2, l2;
                        h2.x = __float2half_rn(v0); h2.y = __float2half_rn(v1);
                        l2.x = __float2half_rn(v0 - __half2float(h2.x));
                        l2.y = __float2half_rn(v1 - __half2float(h2.y));
                        *reinterpret_cast<__half2*>(Ohi + (size_t)r * BN + col) = h2;
                        *reinterpret_cast<__half2*>(Olo + (size_t)r * BN + col) = l2;
                    }
                }
            }
        }
    } else {
#pragma unroll
        for (int mi = 0; mi < MI; mi++) {
            int r0 = bm + wm + mi * 16 + g;
            int r1 = r0 + 8;
#pragma unroll
            for (int nb = 0; nb < 4; nb++) {
                int col = bn + wn + nb * 8 + 2 * t;
                if (r0 < M)
                    *reinterpret_cast<float2*>(C + (size_t)r0 * 512 + col) =
                        make_float2(acc[mi][nb][0], acc[mi][nb][1]);
                if (r1 < M)
                    *reinterpret_cast<float2*>(C + (size_t)r1 * 512 + col) =
                        make_float2(acc[mi][nb][2], acc[mi][nb][3]);
            }
        }
        if (FUSE) {
            int hh = (bn + wn) >> 6;
            float av[4][2], rv[4][2];
#pragma unroll
            for (int nb = 0; nb < 4; nb++)
#pragma unroll
                for (int k = 0; k < 2; k++) {
                    int colh = (wn & 63) + nb * 8 + 2 * t + k;
                    av[nb][k] = al[hh * 64 + colh];
                    rv[nb][k] = ar[hh * 64 + colh];
                }
#pragma unroll
            for (int mi = 0; mi < MI; mi++) {
                float pel0 = 0.f, per0 = 0.f, pel1 = 0.f, per1 = 0.f;
#pragma unroll
                for (int nb = 0; nb < 4; nb++) {
                    pel0 += acc[mi][nb][0] * av[nb][0] + acc[mi][nb][1] * av[nb][1];
                    per0 += acc[mi][nb][0] * rv[nb][0] + acc[mi][nb][1] * rv[nb][1];
                    pel1 += acc[mi][nb][2] * av[nb][0] + acc[mi][nb][3] * av[nb][1];
                    per1 += acc[mi][nb][2] * rv[nb][0] + acc[mi][nb][3] * rv[nb][1];
                }
#pragma unroll
                for (int off = 1; off <= 2; off <<= 1) {
                    pel0 += __shfl_xor_sync(0xffffffffu, pel0, off);
                    per0 += __shfl_xor_sync(0xffffffffu, per0, off);
                    pel1 += __shfl_xor_sync(0xffffffffu, pel1, off);
                    per1 += __shfl_xor_sync(0xffffffffu, per1, off);
                }
                if (t == 0) {
                    int r0 = bm + wm + mi * 16 + g;
                    int r1 = r0 + 8;
                    if (r0 < M) {
                        atomicAdd(&el[r0 * HEADS + hh], pel0);
                        atomicAdd(&er[r0 * HEADS + hh], per0);
                    }
                    if (r1 < M) {
                        atomicAdd(&el[r1 * HEADS + hh], pel1);
                        atomicAdd(&er[r1 * HEADS + hh], per1);
                    }
                }
            }
        }
    }
}

// ---------------- fused edge-softmax + aggregation (head-pair, float4) ------
__device__ __forceinline__ float lrelu(float x) { return x > 0.f ? x : 0.2f * x; }

__global__ void k_attn(const float* __restrict__ feat, const float* __restrict__ bias,
                       const float* __restrict__ el, const float* __restrict__ er,
                       __half* __restrict__ Ohi, __half* __restrict__ Olo)
{
    int n = blockIdx.x;
    int p = threadIdx.y;                 // head pair: heads 2p, 2p+1
    int lane = threadIdx.x;
    int start = g_rowptr[n], end = g_rowptr[n + 1];
    int deg = end - start;
    float er0 = er[n * HEADS + 2 * p];
    float er1 = er[n * HEADS + 2 * p + 1];
    const int doff = p * 128 + lane * 4; // head 2p: lanes 0-15, head 2p+1: lanes 16-31
    const bool loH = (lane < 16);

    float acc0 = 0.f, acc1 = 0.f, acc2 = 0.f, acc3 = 0.f;

    if (deg <= 32) {
        int s = 0;
        float e0 = -INFINITY, e1 = -INFINITY;
        if (lane < deg) {
            s = g_csrsrc[start + lane];
            float2 t = *reinterpret_cast<const float2*>(el + s * HEADS + 2 * p);
            e0 = lrelu(t.x + er0);
            e1 = lrelu(t.y + er1);
        }
        float m0 = e0, m1 = e1;
#pragma unroll
        for (int o = 16; o; o >>= 1) {
            m0 = fmaxf(m0, __shfl_xor_sync(0xffffffffu, m0, o));
            m1 = fmaxf(m1, __shfl_xor_sync(0xffffffffu, m1, o));
        }
        float ws0 = (lane < deg) ? __expf(e0 - m0) : 0.f;
        float ws1 = (lane < deg) ? __expf(e1 - m1) : 0.f;
        float d0 = ws0, d1 = ws1;
#pragma unroll
        for (int o = 16; o; o >>= 1) {
            d0 += __shfl_xor_sync(0xffffffffu, d0, o);
            d1 += __shfl_xor_sync(0xffffffffu, d1, o);
        }
        float w0 = ws0 / fmaxf(d0, 1e-9f);
        float w1 = ws1 / fmaxf(d1, 1e-9f);

        int j = 0;
        for (; j + 4 <= deg; j += 4) {
            int sA = __shfl_sync(0xffffffffu, s, j + 0);
            int sB = __shfl_sync(0xffffffffu, s, j + 1);
            int sC = __shfl_sync(0xffffffffu, s, j + 2);
            int sD = __shfl_sync(0xffffffffu, s, j + 3);
            // convergent shuffles, then per-lane select
            float wA0 = __shfl_sync(0xffffffffu, w0, j + 0);
            float wA1 = __shfl_sync(0xffffffffu, w1, j + 0);
            float wB0 = __shfl_sync(0xffffffffu, w0, j + 1);
            float wB1 = __shfl_sync(0xffffffffu, w1, j + 1);
            float wC0 = __shfl_sync(0xffffffffu, w0, j + 2);
            float wC1 = __shfl_sync(0xffffffffu, w1, j + 2);
            float wD0 = __shfl_sync(0xffffffffu, w0, j + 3);
            float wD1 = __shfl_sync(0xffffffffu, w1, j + 3);
            float wA = loH ? wA0 : wA1;
            float wB = loH ? wB0 : wB1;
            float wC = loH ? wC0 : wC1;
            float wD = loH ? wD0 : wD1;
            float4 vA = *reinterpret_cast<const float4*>(feat + (size_t)sA * 512 + doff);
            float4 vB = *reinterpret_cast<const float4*>(feat + (size_t)sB * 512 + doff);
            float4 vC = *reinterpret_cast<const float4*>(feat + (size_t)sC * 512 + doff);
            float4 vD = *reinterpret_cast<const float4*>(feat + (size_t)sD * 512 + doff);
            acc0 += wA * vA.x + wB * vB.x + wC * vC.x + wD * vD.x;
            acc1 += wA * vA.y + wB * vB.y + wC * vC.y + wD * vD.y;
            acc2 += wA * vA.z + wB * vB.z + wC * vC.z + wD * vD.z;
            acc3 += wA * vA.w + wB * vB.w + wC * vC.w + wD * vD.w;
        }
        for (; j < deg; j++) {
            int   sj = __shfl_sync(0xffffffffu, s, j);
            float t0 = __shfl_sync(0xffffffffu, w0, j);
            float t1 = __shfl_sync(0xffffffffu, w1, j);
            float wj = loH ? t0 : t1;
            float4 v = *reinterpret_cast<const float4*>(feat + (size_t)sj * 512 + doff);
            acc0 += wj * v.x; acc1 += wj * v.y; acc2 += wj * v.z; acc3 += wj * v.w;
        }
    } else {
        float m0 = -INFINITY, m1 = -INFINITY;
        for (int j = start + lane; j < end; j += 32) {
            int s = g_csrsrc[j];
            float2 t = *reinterpret_cast<const float2*>(el + s * HEADS + 2 * p);
            m0 = fmaxf(m0, lrelu(t.x + er0));
            m1 = fmaxf(m1, lrelu(t.y + er1));
        }
#pragma unroll
        for (int o = 16; o; o >>= 1) {
            m0 = fmaxf(m0, __shfl_xor_sync(0xffffffffu, m0, o));
            m1 = fmaxf(m1, __shfl_xor_sync(0xffffffffu, m1, o));
        }
        float d0 = 0.f, d1 = 0.f;
        for (int j = start + lane; j < end; j += 32) {
            int s = g_csrsrc[j];
            float2 t = *reinterpret_cast<const float2*>(el + s * HEADS + 2 * p);
            d0 += __expf(lrelu(t.x + er0) - m0);
            d1 += __expf(lrelu(t.y + er1) - m1);
        }
#pragma unroll
        for (int o = 16; o; o >>= 1) {
            d0 += __shfl_xor_sync(0xffffffffu, d0, o);
            d1 += __shfl_xor_sync(0xffffffffu, d1, o);
        }
        float inv0 = 1.0f / fmaxf(d0, 1e-9f);
        float inv1 = 1.0f / fmaxf(d1, 1e-9f);

        for (int j0 = start; j0 < end; j0 += 32) {
            int jmax = end - j0; if (jmax > 32) jmax = 32;
            int s_l = 0; float wl0 = 0.f, wl1 = 0.f;
            if (lane < jmax) {
                s_l = g_csrsrc[j0 + lane];
                float2 t = *reinterpret_cast<const float2*>(el + s_l * HEADS + 2 * p);
                wl0 = __expf(lrelu(t.x + er0) - m0) * inv0;
                wl1 = __expf(lrelu(t.y + er1) - m1) * inv1;
            }
            for (int jj = 0; jj < jmax; jj++) {
                int   sj = __shfl_sync(0xffffffffu, s_l, jj);
                float t0 = __shfl_sync(0xffffffffu, wl0, jj);
                float t1 = __shfl_sync(0xffffffffu, wl1, jj);
                float wj = loH ? t0 : t1;
                float4 v = *reinterpret_cast<const float4*>(feat + (size_t)sj * 512 + doff);
                acc0 += wj * v.x; acc1 += wj * v.y; acc2 += wj * v.z; acc3 += wj * v.w;
            }
        }
    }

    float4 bv = *reinterpret_cast<const float4*>(bias + doff);
    float o0 = acc0 + bv.x, o1 = acc1 + bv.y, o2 = acc2 + bv.z, o3 = acc3 + bv.w;
    o0 = o0 > 0.f ? o0 : (__expf(o0) - 1.f);
    o1 = o1 > 0.f ? o1 : (__expf(o1) - 1.f);
    o2 = o2 > 0.f ? o2 : (__expf(o2) - 1.f);
    o3 = o3 > 0.f ? o3 : (__expf(o3) - 1.f);
    __half2 h01, h23, l01, l23;
    h01.x = __float2half_rn(o0); h01.y = __float2half_rn(o1);
    h23.x = __float2half_rn(o2); h23.y = __float2half_rn(o3);
    l01.x = __float2half_rn(o0 - __half2float(h01.x));
    l01.y = __float2half_rn(o1 - __half2float(h01.y));
    l23.x = __float2half_rn(o2 - __half2float(h23.x));
    l23.y = __float2half_rn(o3 - __half2float(h23.y));
    size_t o = (size_t)n * 512 + doff;
    uint2 hp, lp;
    hp.x = *reinterpret_cast<uint32_t*>(&h01);
    hp.y = *reinterpret_cast<uint32_t*>(&h23);
    lp.x = *reinterpret_cast<uint32_t*>(&l01);
    lp.y = *reinterpret_cast<uint32_t*>(&l23);
    *reinterpret_cast<uint2*>(Ohi + o) = hp;
    *reinterpret_cast<uint2*>(Olo + o) = lp;
}

// ---------------- skinny GEMM + fused el/er (layer 2) ------------------------
__global__ __launch_bounds__(256) void k_gemm_n10(
    const __half* __restrict__ Ahi, const __half* __restrict__ Alo,
    const float* __restrict__ B, float* __restrict__ C,
    const float* __restrict__ al2, const float* __restrict__ ar2,
    float* __restrict__ el, float* __restrict__ er, int M)
{
    __shared__ float Bs[512 * 10];
    int tid = threadIdx.x;
    for (int i = tid; i < 512 * 10; i += 256) Bs[i] = B[i];
    __syncthreads();
    int warp = tid >> 5, lane = tid & 31;
    int row = blockIdx.x * 8 + warp;
    if (row >= M) return;
    float acc[10];
#pragma unroll
    for (int c = 0; c < 10; c++) acc[c] = 0.0f;
#pragma unroll
    for (int i = 0; i < 8; i++) {
        int k = lane * 2 + i * 64;
        __half2 h2 = *reinterpret_cast<const __half2*>(Ahi + (size_t)row * 512 + k);
        __half2 l2 = *reinterpret_cast<const __half2*>(Alo + (size_t)row * 512 + k);
        float a0 = __half2float(h2.x) + __half2float(l2.x);
        float a1 = __half2float(h2.y) + __half2float(l2.y);
#pragma unroll
        for (int c = 0; c < 10; c++)
            acc[c] += a0 * Bs[k * 10 + c] + a1 * Bs[(k + 1) * 10 + c];
    }
#pragma unroll
    for (int c = 0; c < 10; c++)
#pragma unroll
        for (int o = 16; o; o >>= 1) acc[c] += __shfl_xor_sync(0xffffffffu, acc[c], o);
    if (lane == 0) {
        float e_l = 0.f, e_r = 0.f;
#pragma unroll
        for (int c = 0; c < 10; c++) {
            C[(size_t)row * 10 + c] = acc[c];
            e_l += acc[c] * al2[c];
            e_r += acc[c] * ar2[c];
        }
        el[row] = e_l;
        er[row] = e_r;
    }
}

// ---------------- layer-2 agg (D=10, f32 out) --------------------------------
__global__ void k_agg10(const float* __restrict__ feat, const float* __restrict__ bias,
                        const float* __restrict__ el, const float* __restrict__ er,
                        float* __restrict__ out)
{
    int n = blockIdx.x;
    int lane = threadIdx.x;
    int start = g_rowptr[n], end = g_rowptr[n + 1];
    float er_h = er[n];

    float m = -INFINITY;
    for (int j = start + lane; j < end; j += 32)
        m = fmaxf(m, lrelu(el[g_csrsrc[j]] + er_h));
#pragma unroll
    for (int o = 16; o; o >>= 1) m = fmaxf(m, __shfl_xor_sync(0xffffffffu, m, o));

    float dsum = 0.f;
    for (int j = start + lane; j < end; j += 32)
        dsum += __expf(lrelu(el[g_csrsrc[j]] + er_h) - m);
#pragma unroll
    for (int o = 16; o; o >>= 1) dsum += __shfl_xor_sync(0xffffffffu, dsum, o);
    float inv = 1.0f / fmaxf(dsum, 1e-9f);

    float acc = 0.f;
    for (int j0 = start; j0 < end; j0 += 32) {
        int jmax = end - j0; if (jmax > 32) jmax = 32;
        int s_l = 0; float w_l = 0.f;
        if (lane < jmax) {
            s_l = g_csrsrc[j0 + lane];
            w_l = __expf(lrelu(el[s_l] + er_h) - m);
        }
        for (int jj = 0; jj < jmax; jj++) {
            int   s = __shfl_sync(0xffffffffu, s_l, jj);
            float w = __shfl_sync(0xffffffffu, w_l, jj);
            if (lane < NCLS) acc += w * feat[(size_t)s * NCLS + lane];
        }
    }
    if (lane < NCLS) out[(size_t)n * NCLS + lane] = acc * inv + bias[lane];
}

// ---------------- launcher ----------------------------------------------------
extern "C" void kernel_launch(void* const* d_in, const int* in_sizes, int n_in,
                              void* d_out, int out_size)
{
    const float* feat0 = (const float*)d_in[0];
    const float* feat1 = (const float*)d_in[1];
    const float* fc0w  = (const float*)d_in[2];
    const float* fc0b  = (const float*)d_in[3];
    const float* fc1w  = (const float*)d_in[4];
    const float* fc1b  = (const float*)d_in[5];
    const float* W0    = (const float*)d_in[6];
    const float* al0   = (const float*)d_in[7];
    const float* ar0   = (const float*)d_in[8];
    const float* b0    = (const float*)d_in[9];
    const float* W1    = (const float*)d_in[10];
    const float* al1   = (const float*)d_in[11];
    const float* ar1   = (const float*)d_in[12];
    const float* b1    = (const float*)d_in[13];
    const float* W2    = (const float*)d_in[14];
    const float* al2   = (const float*)d_in[15];
    const float* ar2   = (const float*)d_in[16];
    const float* b2    = (const float*)d_in[17];
    const int*   ei    = (const int*)d_in[18];

    const int E = in_sizes[18] / 2;
    const int M0 = in_sizes[0] / 256;   // 30000
    const int M1 = in_sizes[1] / 128;   // 20000
    const int* src = ei;
    const int* dst = ei + E;

    float *bufA, *bufB, *elA, *erA, *elB, *erB;
    __half *fhi, *flo, *hhi, *hlo, *ahi, *alo;
    __half *wf0h, *wf0l, *wf1h, *wf1l, *w0th, *w0tl, *w1th, *w1tl;
    cudaGetSymbolAddress((void**)&bufA, g_bufA);
    cudaGetSymbolAddress((void**)&bufB, g_bufB);
    cudaGetSymbolAddress((void**)&elA,  g_elA);
    cudaGetSymbolAddress((void**)&erA,  g_erA);
    cudaGetSymbolAddress((void**)&elB,  g_elB);
    cudaGetSymbolAddress((void**)&erB,  g_erB);
    cudaGetSymbolAddress((void**)&fhi,  g_f_hi);
    cudaGetSymbolAddress((void**)&flo,  g_f_lo);
    cudaGetSymbolAddress((void**)&hhi,  g_h_hi);
    cudaGetSymbolAddress((void**)&hlo,  g_h_lo);
    cudaGetSymbolAddress((void**)&ahi,  g_a_hi);
    cudaGetSymbolAddress((void**)&alo,  g_a_lo);
    cudaGetSymbolAddress((void**)&wf0h, g_wf0_hi);
    cudaGetSymbolAddress((void**)&wf0l, g_wf0_lo);
    cudaGetSymbolAddress((void**)&wf1h, g_wf1_hi);
    cudaGetSymbolAddress((void**)&wf1l, g_wf1_lo);
    cudaGetSymbolAddress((void**)&w0th, g_w0t_hi);
    cudaGetSymbolAddress((void**)&w0tl, g_w0t_lo);
    cudaGetSymbolAddress((void**)&w1th, g_w1t_hi);
    cudaGetSymbolAddress((void**)&w1tl, g_w1t_lo);

    float* outp = (float*)d_out;

    constexpr int SMEM_MM = STG * 18432;   // 73728 for all variants
    cudaFuncSetAttribute((const void*)&k_mma<256, 64, false, true, 3>,
                         cudaFuncAttributeMaxDynamicSharedMemorySize, SMEM_MM);
    cudaFuncSetAttribute((const void*)&k_mma<128, 64, false, true, 3>,
                         cudaFuncAttributeMaxDynamicSharedMemorySize, SMEM_MM);
    cudaFuncSetAttribute((const void*)&k_mma<64, 128, true, false, 2>,
                         cudaFuncAttributeMaxDynamicSharedMemorySize, SMEM_MM);
    cudaFuncSetAttribute((const void*)&k_mma<512, 128, true, false, 2>,
                         cudaFuncAttributeMaxDynamicSharedMemorySize, SMEM_MM);

    // fork side streams off the (possibly capturing) default stream
    cudaStream_t sB, sC;
    cudaStreamCreateWithFlags(&sB, cudaStreamNonBlocking);
    cudaStreamCreateWithFlags(&sC, cudaStreamNonBlocking);
    cudaEvent_t evFork, evB, evC0, evC;
    cudaEventCreateWithFlags(&evFork, cudaEventDisableTiming);
    cudaEventCreateWithFlags(&evB,    cudaEventDisableTiming);
    cudaEventCreateWithFlags(&evC0,   cudaEventDisableTiming);
    cudaEventCreateWithFlags(&evC,    cudaEventDisableTiming);
    cudaEventRecord(evFork, 0);
    cudaStreamWaitEvent(sB, evFork, 0);
    cudaStreamWaitEvent(sC, evFork, 0);

    // main stream, launches 0..3 (index 3 = profiled proj0 mma)
    k_asplit<<<(M0 * 256 / 4 + 255) / 256, 256>>>(feat0, fhi, flo, M0 * 256);
    k_asplit<<<(M1 * 128 / 4 + 255) / 256, 256>>>(feat1, fhi + F0SZ, flo + F0SZ, M1 * 128);
    k_tsplit<<<dim3(2, 8),  dim3(32, 32)>>>(fc0w, wf0h, wf0l, 256, 64);
    k_mma<256, 64, false, true, 3><<<dim3(1, 235), 256, SMEM_MM>>>(
        fhi, flo, wf0h, wf0l, nullptr, hhi, hlo, fc0b,
        nullptr, nullptr, nullptr, nullptr, M0);

    // side stream B: CSR build
    k_zero_deg<<<(NN + 255) / 256, 256, 0, sB>>>();
    k_count<<<(E + 255) / 256, 256, 0, sB>>>(dst, E);
    k_scan1<<<NBLK, 256, 0, sB>>>();
    k_scan2<<<1, 256, 0, sB>>>();
    k_scan3<<<NBLK, 256, 0, sB>>>();
    k_scatter<<<(E + 255) / 256, 256, 0, sB>>>(src, dst, E);
    cudaEventRecord(evB, sB);

    // side stream C: el/er zero + W0 split (evC0), then W1 split (evC)
    k_zero_el<<<(NN * HEADS + 255) / 256, 256, 0, sC>>>();
    k_tsplit<<<dim3(16, 2),  dim3(32, 32), 0, sC>>>(W0, w0th, w0tl, 64, 512);
    cudaEventRecord(evC0, sC);
    k_tsplit<<<dim3(16, 16), dim3(32, 32), 0, sC>>>(W1, w1th, w1tl, 512, 512);
    cudaEventRecord(evC, sC);

    // main stream continues: proj1
    k_tsplit<<<dim3(2, 4), dim3(32, 32)>>>(fc1w, wf1h, wf1l, 128, 64);
    k_mma<128, 64, false, true, 3><<<dim3(1, 157), 256, SMEM_MM>>>(
        fhi + F0SZ, flo + F0SZ, wf1h, wf1l, nullptr,
        hhi + (size_t)M0 * 64, hlo + (size_t)M0 * 64, fc1b,
        nullptr, nullptr, nullptr, nullptr, M1);

    // join C0 (W0 split + zeros) before layer-0 mma
    cudaStreamWaitEvent(0, evC0, 0);
    k_mma<64, 128, true, false, 2><<<dim3(4, 391), 256, SMEM_MM>>>(
        hhi, hlo, w0th, w0tl, bufA, nullptr, nullptr, nullptr,
        al0, ar0, elA, erA, NN);

    // join B (CSR) before attention
    cudaStreamWaitEvent(0, evB, 0);
    k_attn<<<NN, dim3(32, 4)>>>(bufA, b0, elA, erA, ahi, alo);

    // join C (W1 split) before layer-1 mma
    cudaStreamWaitEvent(0, evC, 0);
    k_mma<512, 128, true, false, 2><<<dim3(4, 391), 256, SMEM_MM>>>(
        ahi, alo, w1th, w1tl, bufA, nullptr, nullptr, nullptr,
        al1, ar1, elB, erB, NN);
    k_attn<<<NN, dim3(32, 4)>>>(bufA, b1, elB, erB, ahi, alo);

    // layer 2
    k_gemm_n10<<<(NN + 7) / 8, 256>>>(ahi, alo, W2, bufB, al2, ar2, elA, erA, NN);
    k_agg10<<<NN, 32>>>(bufB, b2, elA, erA, outp);

    cudaEventDestroy(evFork);
    cudaEventDestroy(evB);
    cudaEventDestroy(evC0);
    cudaEventDestroy(evC);
    cudaStreamDestroy(sB);
    cudaStreamDestroy(sC);

    (void)n_in; (void)out_size;
}